// round 9
// baseline (speedup 1.0000x reference)
#include <cuda_runtime.h>
#include <cuda_bf16.h>
#include <cstdint>

#define B_SZ 4096
#define D_SZ 2048
#define E_SZ 16
#define C_SZ 1000
#define NPAD 1024

#define TM 128
#define TN 256
#define KC 32
#define NCHUNK (D_SZ / KC)      // 64

// smem row = 32 bf16 = 64B, padded to 80B (5x16B -> ldmatrix conflict-free)
#define ROWB 80
#define A_TILE_B (128 * ROWB)   // 10240
#define B_TILE_B (256 * ROWB)   // 20480
#define OFF_AH 0
#define OFF_AL A_TILE_B
#define OFF_BH (2 * A_TILE_B)
#define OFF_BL (2 * A_TILE_B + B_TILE_B)
#define STAGE_B (2 * A_TILE_B + 2 * B_TILE_B)   // 61440
#define DYN_BYTES (2 * STAGE_B)                 // 122880

// ---------------- scratch ----------------
__device__ int   g_cnt[E_SZ];
__device__ int   g_rows[E_SZ * B_SZ];
__device__ float g_rw[E_SZ * B_SZ];
// pre-converted bf16 hi/lo operands
__device__ __nv_bfloat16 x_h[(size_t)B_SZ * D_SZ];
__device__ __nv_bfloat16 x_l[(size_t)B_SZ * D_SZ];
__device__ __nv_bfloat16 w_h[(size_t)E_SZ * NPAD * D_SZ];   // [e][n][k]
__device__ __nv_bfloat16 w_l[(size_t)E_SZ * NPAD * D_SZ];

// ---------------- helpers ----------------
__device__ __forceinline__ uint32_t smem_u32(const void* p) {
    uint32_t a;
    asm("{ .reg .u64 t; cvta.to.shared.u64 t, %1; cvt.u32.u64 %0, t; }"
        : "=r"(a) : "l"(p));
    return a;
}
__device__ __forceinline__ void split_pack(float a, float b, uint32_t& h, uint32_t& l) {
    __nv_bfloat162 hh = __floats2bfloat162_rn(a, b);
    float ra = a - __bfloat162float(hh.x);
    float rb = b - __bfloat162float(hh.y);
    __nv_bfloat162 ll = __floats2bfloat162_rn(ra, rb);
    h = *reinterpret_cast<uint32_t*>(&hh);
    l = *reinterpret_cast<uint32_t*>(&ll);
}
__device__ __forceinline__ void cpa16(uint32_t dst, const void* src) {
    asm volatile("cp.async.ca.shared.global [%0], [%1], 16;"
                 :: "r"(dst), "l"(src));
}
#define CP_COMMIT() asm volatile("cp.async.commit_group;" ::: "memory")
#define CP_WAIT1()  asm volatile("cp.async.wait_group 1;" ::: "memory")
#define CP_WAIT0()  asm volatile("cp.async.wait_group 0;" ::: "memory")
#define LDSM4(r, addr)                                                        \
    asm volatile("ldmatrix.sync.aligned.m8n8.x4.shared.b16 {%0,%1,%2,%3}, [%4];" \
                 : "=r"((r)[0]), "=r"((r)[1]), "=r"((r)[2]), "=r"((r)[3])     \
                 : "r"(addr))
#define MMA16816(c, a, b0, b1)                                                \
    asm volatile("mma.sync.aligned.m16n8k16.row.col.f32.bf16.bf16.f32 "       \
                 "{%0,%1,%2,%3}, {%4,%5,%6,%7}, {%8,%9}, {%0,%1,%2,%3};"      \
                 : "+f"((c)[0]), "+f"((c)[1]), "+f"((c)[2]), "+f"((c)[3])     \
                 : "r"((a)[0]), "r"((a)[1]), "r"((a)[2]), "r"((a)[3]),        \
                   "r"(b0), "r"(b1))

// ---------------- kernel 1: zero output + expert counts ----------------
__global__ void zero_kernel(float4* __restrict__ out, int n4) {
    int i = blockIdx.x * blockDim.x + threadIdx.x;
    if (i < n4) out[i] = make_float4(0.f, 0.f, 0.f, 0.f);
    if (i < E_SZ) g_cnt[i] = 0;
}

// ---------------- kernel 2: convert x -> bf16 hi/lo ----------------
__global__ void conv_x(const float4* __restrict__ xin, int n4) {
    int i = blockIdx.x * blockDim.x + threadIdx.x;
    if (i >= n4) return;
    float4 v = xin[i];
    uint32_t h0, l0, h1, l1;
    split_pack(v.x, v.y, h0, l0);
    split_pack(v.z, v.w, h1, l1);
    reinterpret_cast<uint2*>(x_h)[i] = make_uint2(h0, h1);
    reinterpret_cast<uint2*>(x_l)[i] = make_uint2(l0, l1);
}

// ---------------- kernel 3: convert + transpose We -> [e][n][k] bf16 -------
__global__ __launch_bounds__(256) void conv_w(const float* __restrict__ We) {
    const int e  = blockIdx.z;
    const int k0 = blockIdx.y * 32;
    const int n0 = blockIdx.x * 128;
    const int tid = threadIdx.x;

    __shared__ float xs[32][132];

    const float* src = We + ((size_t)e * D_SZ + k0) * C_SZ + n0;
    for (int i = tid; i < 32 * 128; i += 256) {
        int k = i >> 7, n = i & 127;
        xs[k][n] = (n0 + n < C_SZ) ? src[(size_t)k * C_SZ + n] : 0.0f;
    }
    __syncthreads();

    const int n    = tid >> 1;
    const int kb   = (tid & 1) * 16;
    uint32_t h[8], l[8];
#pragma unroll
    for (int j = 0; j < 8; j++)
        split_pack(xs[kb + 2 * j][n], xs[kb + 2 * j + 1][n], h[j], l[j]);

    const size_t base = ((size_t)(e * NPAD + n0 + n) * D_SZ + k0 + kb);
    *reinterpret_cast<uint4*>(w_h + base)     = make_uint4(h[0], h[1], h[2], h[3]);
    *reinterpret_cast<uint4*>(w_h + base + 8) = make_uint4(h[4], h[5], h[6], h[7]);
    *reinterpret_cast<uint4*>(w_l + base)     = make_uint4(l[0], l[1], l[2], l[3]);
    *reinterpret_cast<uint4*>(w_l + base + 8) = make_uint4(l[4], l[5], l[6], l[7]);
}

// ---------------- kernel 4: fused gating + top-2 softmax + bucket ----------
#define GR 32
__global__ __launch_bounds__(256) void gate_fused(
    const float* __restrict__ x, const float* __restrict__ Wr,
    const float* __restrict__ br)
{
    __shared__ __align__(16) float xs[GR][132];
    __shared__ __align__(16) float wrs[E_SZ][132];
    __shared__ float lg[GR][17];

    const int tid  = threadIdx.x;
    const int row0 = blockIdx.x * GR;
    const int e    = tid & 15;
    const int g    = tid >> 4;

    float acc0 = 0.0f, acc1 = 0.0f;

    for (int ch = 0; ch < D_SZ / 128; ch++) {
        const int d0 = ch * 128;
        for (int i = tid; i < GR * 32; i += 256) {
            int rr = i >> 5, d4 = (i & 31) * 4;
            *reinterpret_cast<float4*>(&xs[rr][d4]) =
                *reinterpret_cast<const float4*>(
                    x + (size_t)(row0 + rr) * D_SZ + d0 + d4);
        }
        for (int i = tid; i < 128 * 4; i += 256) {
            int d = i >> 2, e4 = (i & 3) * 4;
            float4 v = *reinterpret_cast<const float4*>(
                Wr + (size_t)(d0 + d) * E_SZ + e4);
            wrs[e4 + 0][d] = v.x; wrs[e4 + 1][d] = v.y;
            wrs[e4 + 2][d] = v.z; wrs[e4 + 3][d] = v.w;
        }
        __syncthreads();
#pragma unroll 8
        for (int d = 0; d < 128; d += 4) {
            float4 w4 = *reinterpret_cast<const float4*>(&wrs[e][d]);
            float4 x0 = *reinterpret_cast<const float4*>(&xs[2 * g][d]);
            float4 x1 = *reinterpret_cast<const float4*>(&xs[2 * g + 1][d]);
            acc0 += x0.x * w4.x + x0.y * w4.y + x0.z * w4.z + x0.w * w4.w;
            acc1 += x1.x * w4.x + x1.y * w4.y + x1.z * w4.z + x1.w * w4.w;
        }
        __syncthreads();
    }
    lg[2 * g][e]     = acc0 + br[e];
    lg[2 * g + 1][e] = acc1 + br[e];
    __syncthreads();

    if (tid < GR) {
        const int r = row0 + tid;
        float best = -1e30f; int bi = 0;
#pragma unroll
        for (int k = 0; k < E_SZ; k++) {
            float v = lg[tid][k];
            if (v > best) { best = v; bi = k; }
        }
        float sec = -1e30f; int si = 0;
#pragma unroll
        for (int k = 0; k < E_SZ; k++) {
            if (k == bi) continue;
            float v = lg[tid][k];
            if (v > sec) { sec = v; si = k; }
        }
        float t   = expf(sec - best);
        float inv = 1.0f / (1.0f + t);
        int p0 = atomicAdd(&g_cnt[bi], 1);
        g_rows[bi * B_SZ + p0] = r;  g_rw[bi * B_SZ + p0] = inv;
        int p1 = atomicAdd(&g_cnt[si], 1);
        g_rows[si * B_SZ + p1] = r;  g_rw[si * B_SZ + p1] = t * inv;
    }
}

// ---------------- kernel 5: cp.async mma.sync grouped gather-GEMM ----------
extern __shared__ char dynsmem[];

__global__ __launch_bounds__(256, 1) void expert_gemm_mma(
    const float* __restrict__ be, float* __restrict__ out)
{
    const int e   = blockIdx.z;
    const int cnt = g_cnt[e];
    const int m0  = blockIdx.y * TM;
    if (m0 >= cnt) return;
    const int n0  = blockIdx.x * TN;

    __shared__ int   rs[TM];
    __shared__ float ws[TM];
    __shared__ float bes[TN];

    const int tid  = threadIdx.x;
    const int wid  = tid >> 5;
    const int lane = tid & 31;

    const uint32_t sb0 = smem_u32(dynsmem);

    for (int m = tid; m < TM; m += 256) {
        int gm = m0 + m; int r = -1; float w = 0.0f;
        if (gm < cnt) { r = g_rows[e * B_SZ + gm]; w = g_rw[e * B_SZ + gm]; }
        rs[m] = r; ws[m] = w;
    }
    for (int j = tid; j < TN; j += 256) {
        int c = n0 + j;
        bes[j] = (c < C_SZ) ? be[e * C_SZ + c] : 0.0f;
    }
    __syncthreads();

    // ---- cp.async op mappings (12 x 16B per thread per chunk) ----
    // A: rows ar0 = tid>>2 and ar0+64; seg = tid&3 (16B within the 64B row)
    const int seg = tid & 3;
    const int ar0 = tid >> 2;
    const int ar1 = ar0 + 64;
    int ra0 = rs[ar0]; if (ra0 < 0) ra0 = 0;
    int ra1 = rs[ar1]; if (ra1 < 0) ra1 = 0;
    const char* a0h = (const char*)(x_h + (size_t)ra0 * D_SZ + seg * 8);
    const char* a0l = (const char*)(x_l + (size_t)ra0 * D_SZ + seg * 8);
    const char* a1h = (const char*)(x_h + (size_t)ra1 * D_SZ + seg * 8);
    const char* a1l = (const char*)(x_l + (size_t)ra1 * D_SZ + seg * 8);
    const uint32_t a0d = (uint32_t)(ar0 * ROWB + seg * 16);
    const uint32_t a1d = (uint32_t)(ar1 * ROWB + seg * 16);
    // B: rows bn = tid>>2 + 64j (j=0..3); same seg
    const int bn0 = tid >> 2;
    const char* b0h = (const char*)(w_h + ((size_t)(e * NPAD + n0 + bn0) * D_SZ + seg * 8));
    const char* b0l = (const char*)(w_l + ((size_t)(e * NPAD + n0 + bn0) * D_SZ + seg * 8));
    const size_t   bsrc_step = (size_t)64 * D_SZ * 2;     // 64 n-rows, bytes
    const uint32_t bdst_step = 64 * ROWB;
    const uint32_t b0d = (uint32_t)(bn0 * ROWB + seg * 16);

    auto issue_stage = [&](int c, int s) {
        const uint32_t sb = sb0 + (uint32_t)s * STAGE_B;
        const uint32_t ko = (uint32_t)c * (KC * 2);       // 64 bytes per chunk
        cpa16(sb + OFF_AH + a0d, a0h + ko);
        cpa16(sb + OFF_AH + a1d, a1h + ko);
        cpa16(sb + OFF_AL + a0d, a0l + ko);
        cpa16(sb + OFF_AL + a1d, a1l + ko);
#pragma unroll
        for (int j = 0; j < 4; j++) {
            cpa16(sb + OFF_BH + b0d + j * bdst_step, b0h + j * bsrc_step + ko);
            cpa16(sb + OFF_BL + b0d + j * bdst_step, b0l + j * bsrc_step + ko);
        }
    };

    // ---- compute mappings: 2x4 warp grid, 64x64 warp tiles ----
    const int warp_m = (wid & 1) * 64;
    const int warp_n = (wid >> 1) * 64;
    const uint32_t a_lds =
        (uint32_t)((warp_m + (lane & 15)) * ROWB + (lane >> 4) * 16);
    const uint32_t b_lds =
        (uint32_t)((warp_n + ((lane >> 4) & 1) * 8 + (lane & 7)) * ROWB +
                   ((lane >> 3) & 1) * 16);

    float acc[4][8][4];
#pragma unroll
    for (int i = 0; i < 4; i++)
#pragma unroll
        for (int j = 0; j < 8; j++)
#pragma unroll
            for (int q = 0; q < 4; q++) acc[i][j][q] = 0.0f;

    auto compute_kk = [&](int s, int kk) {
        const uint32_t sb = sb0 + (uint32_t)s * STAGE_B;
        const uint32_t koff = (uint32_t)(kk * 32);
        uint32_t ah[4][4], al[4][4];
#pragma unroll
        for (int mt = 0; mt < 4; mt++) {
            LDSM4(ah[mt], sb + OFF_AH + a_lds + mt * (16 * ROWB) + koff);
            LDSM4(al[mt], sb + OFF_AL + a_lds + mt * (16 * ROWB) + koff);
        }
#pragma unroll
        for (int nh = 0; nh < 2; nh++) {
            uint32_t bh[2][4], bl[2][4];
#pragma unroll
            for (int np = 0; np < 2; np++) {
                const uint32_t ro = (uint32_t)((nh * 2 + np) * (16 * ROWB)) + koff;
                LDSM4(bh[np], sb + OFF_BH + b_lds + ro);
                LDSM4(bl[np], sb + OFF_BL + b_lds + ro);
            }
#pragma unroll
            for (int mt = 0; mt < 4; mt++)
#pragma unroll
                for (int nt2 = 0; nt2 < 4; nt2++) {
                    float* a4 = acc[mt][nh * 4 + nt2];
                    uint32_t* bhf = &bh[nt2 >> 1][(nt2 & 1) * 2];
                    uint32_t* blf = &bl[nt2 >> 1][(nt2 & 1) * 2];
                    MMA16816(a4, ah[mt], bhf[0], bhf[1]);
                    MMA16816(a4, ah[mt], blf[0], blf[1]);
                    MMA16816(a4, al[mt], bhf[0], bhf[1]);
                }
        }
    };

    // ---- main loop: cp.async double-buffer ----
    issue_stage(0, 0);
    CP_COMMIT();
    for (int c = 0; c < NCHUNK; c++) {
        const int s = c & 1;
        if (c + 1 < NCHUNK) {
            issue_stage(c + 1, s ^ 1);
            CP_COMMIT();
            CP_WAIT1();
        } else {
            CP_WAIT0();
        }
        __syncthreads();
        compute_kk(s, 0);
        compute_kk(s, 1);
        __syncthreads();
    }

    // ---- epilogue: weighted atomic scatter ----
    const int gr = lane >> 2;
    const int gc = (lane & 3) * 2;
#pragma unroll
    for (int mt = 0; mt < 4; mt++) {
#pragma unroll
        for (int half = 0; half < 2; half++) {
            const int m = warp_m + mt * 16 + gr + half * 8;
            const int r = rs[m];
            if (r < 0) continue;
            const float w = ws[m];
            float* orow = out + (size_t)r * C_SZ;
#pragma unroll
            for (int nt = 0; nt < 8; nt++) {
                const int cc = warp_n + nt * 8 + gc;
                const int c = n0 + cc;
                if (c >= C_SZ) continue;
                const float v0 = acc[mt][nt][half * 2 + 0];
                const float v1 = acc[mt][nt][half * 2 + 1];
                atomicAdd(orow + c,     w * (v0 + bes[cc]));
                atomicAdd(orow + c + 1, w * (v1 + bes[cc + 1]));
            }
        }
    }
}

// ---------------- launch ----------------
extern "C" void kernel_launch(void* const* d_in, const int* in_sizes, int n_in,
                              void* d_out, int out_size) {
    const float* x  = (const float*)d_in[0];
    const float* Wr = (const float*)d_in[1];
    const float* br = (const float*)d_in[2];
    const float* We = (const float*)d_in[3];
    const float* be = (const float*)d_in[4];
    float* out = (float*)d_out;

    cudaFuncSetAttribute(expert_gemm_mma,
                         cudaFuncAttributeMaxDynamicSharedMemorySize, DYN_BYTES);

    const int n4 = (B_SZ * C_SZ) / 4;
    zero_kernel<<<(n4 + 255) / 256, 256>>>((float4*)out, n4);
    const int nx4 = (B_SZ * D_SZ) / 4;
    conv_x<<<(nx4 + 255) / 256, 256>>>((const float4*)x, nx4);
    dim3 wgrid(NPAD / 128, D_SZ / 32, E_SZ);
    conv_w<<<wgrid, 256>>>(We);
    gate_fused<<<B_SZ / GR, 256>>>(x, Wr, br);
    dim3 grid((C_SZ + TN - 1) / TN, B_SZ / TM, E_SZ);
    expert_gemm_mma<<<grid, 256, DYN_BYTES>>>(be, out);
}

// round 10
// speedup vs baseline: 1.1512x; 1.1512x over previous
#include <cuda_runtime.h>
#include <cuda_bf16.h>
#include <cstdint>

#define B_SZ 4096
#define D_SZ 2048
#define E_SZ 16
#define C_SZ 1000

#define TM 128
#define TN 256
#define KC 32
#define NCHUNK (D_SZ / KC)      // 64

// smem row = 32 bf16 = 64B, padded to 80B (5x16B -> ldmatrix conflict-free)
#define ROWB 80
#define A_TILE_B (128 * ROWB)   // 10240
#define B_TILE_B (256 * ROWB)   // 20480
#define OFF_AH 0
#define OFF_AL A_TILE_B
#define OFF_BH (2 * A_TILE_B)
#define OFF_BL (2 * A_TILE_B + B_TILE_B)
#define STAGE_B (2 * A_TILE_B + 2 * B_TILE_B)   // 61440
#define DYN_BYTES (2 * STAGE_B)                 // 122880

// ---------------- scratch ----------------
__device__ int   g_cnt[E_SZ];
__device__ int   g_rows[E_SZ * B_SZ];
__device__ float g_rw[E_SZ * B_SZ];

// ---------------- helpers ----------------
__device__ __forceinline__ uint32_t smem_u32(const void* p) {
    uint32_t a;
    asm("{ .reg .u64 t; cvta.to.shared.u64 t, %1; cvt.u32.u64 %0, t; }"
        : "=r"(a) : "l"(p));
    return a;
}
__device__ __forceinline__ void split_pack(float a, float b, uint32_t& h, uint32_t& l) {
    __nv_bfloat162 hh = __floats2bfloat162_rn(a, b);
    float ra = a - __bfloat162float(hh.x);
    float rb = b - __bfloat162float(hh.y);
    __nv_bfloat162 ll = __floats2bfloat162_rn(ra, rb);
    h = *reinterpret_cast<uint32_t*>(&hh);
    l = *reinterpret_cast<uint32_t*>(&ll);
}
__device__ __forceinline__ void sts128(uint32_t addr, uint32_t a, uint32_t b,
                                       uint32_t c, uint32_t d) {
    asm volatile("st.shared.v4.b32 [%0], {%1,%2,%3,%4};"
                 :: "r"(addr), "r"(a), "r"(b), "r"(c), "r"(d) : "memory");
}
__device__ __forceinline__ void cpa16(uint32_t dst, const void* src) {
    asm volatile("cp.async.ca.shared.global [%0], [%1], 16;"
                 :: "r"(dst), "l"(src));
}
#define CP_COMMIT() asm volatile("cp.async.commit_group;" ::: "memory")
#define CP_WAIT1()  asm volatile("cp.async.wait_group 1;" ::: "memory")
#define CP_WAIT0()  asm volatile("cp.async.wait_group 0;" ::: "memory")
#define LDSM4(r, addr)                                                        \
    asm volatile("ldmatrix.sync.aligned.m8n8.x4.shared.b16 {%0,%1,%2,%3}, [%4];" \
                 : "=r"((r)[0]), "=r"((r)[1]), "=r"((r)[2]), "=r"((r)[3])     \
                 : "r"(addr))
#define MMA16816(c, a, b0, b1)                                                \
    asm volatile("mma.sync.aligned.m16n8k16.row.col.f32.bf16.bf16.f32 "       \
                 "{%0,%1,%2,%3}, {%4,%5,%6,%7}, {%8,%9}, {%0,%1,%2,%3};"      \
                 : "+f"((c)[0]), "+f"((c)[1]), "+f"((c)[2]), "+f"((c)[3])     \
                 : "r"((a)[0]), "r"((a)[1]), "r"((a)[2]), "r"((a)[3]),        \
                   "r"(b0), "r"(b1))

// ---------------- kernel 1: zero output + expert counts ----------------
__global__ void zero_kernel(float4* __restrict__ out, int n4) {
    int i = blockIdx.x * blockDim.x + threadIdx.x;
    if (i < n4) out[i] = make_float4(0.f, 0.f, 0.f, 0.f);
    if (i < E_SZ) g_cnt[i] = 0;
}

// ---------------- kernel 2: pipelined gating + top-2 softmax + bucket ------
// 256 blocks x 16 rows. cp.async double-buffers the x chunk; Wr chunk is
// register-prefetched and STS-transposed. DRAM latency of the next chunk is
// hidden under compute of the current one (R9's gate exposed it: 68us).
#define GR 16
__global__ __launch_bounds__(256) void gate_fused(
    const float* __restrict__ x, const float* __restrict__ Wr,
    const float* __restrict__ br)
{
    __shared__ __align__(16) float xs[2][GR][132];
    __shared__ __align__(16) float wrs[2][E_SZ][132];
    __shared__ float lg[GR][17];

    const int tid  = threadIdx.x;
    const int row0 = blockIdx.x * GR;
    const int e    = tid & 15;
    const int r    = tid >> 4;

    // xs staging: thread owns row (tid>>4), segs (tid&15) and (tid&15)+16
    const int xrow = tid >> 4;
    const int xseg = tid & 15;
    const float* xsrc = x + (size_t)(row0 + xrow) * D_SZ;
    // Wr staging: thread owns d = tid>>1, e-half = (tid&1)*8
    const int wd = tid >> 1;
    const int we = (tid & 1) * 8;

    float4 wr0, wr1;
    auto ldg_wr = [&](int ch) {
        const float* p = Wr + (size_t)(ch * 128 + wd) * E_SZ + we;
        wr0 = *reinterpret_cast<const float4*>(p);
        wr1 = *reinterpret_cast<const float4*>(p + 4);
    };
    auto sts_wr = [&](int s) {
        wrs[s][we + 0][wd] = wr0.x; wrs[s][we + 1][wd] = wr0.y;
        wrs[s][we + 2][wd] = wr0.z; wrs[s][we + 3][wd] = wr0.w;
        wrs[s][we + 4][wd] = wr1.x; wrs[s][we + 5][wd] = wr1.y;
        wrs[s][we + 6][wd] = wr1.z; wrs[s][we + 7][wd] = wr1.w;
    };
    auto cpa_xs = [&](int ch, int s) {
        const int d0 = ch * 128;
        cpa16(smem_u32(&xs[s][xrow][xseg * 4]),        xsrc + d0 + xseg * 4);
        cpa16(smem_u32(&xs[s][xrow][(xseg + 16) * 4]), xsrc + d0 + (xseg + 16) * 4);
    };

    float acc0 = 0.0f, acc1 = 0.0f;

    ldg_wr(0);
    cpa_xs(0, 0); CP_COMMIT();
    for (int ch = 0; ch < D_SZ / 128; ch++) {
        const int s = ch & 1;
        sts_wr(s);
        if (ch + 1 < D_SZ / 128) {
            ldg_wr(ch + 1);
            cpa_xs(ch + 1, s ^ 1); CP_COMMIT();
            CP_WAIT1();
        } else {
            CP_WAIT0();
        }
        __syncthreads();
#pragma unroll
        for (int d = 0; d < 64; d += 4) {
            float4 xa = *reinterpret_cast<const float4*>(&xs[s][r][d]);
            float4 wa = *reinterpret_cast<const float4*>(&wrs[s][e][d]);
            acc0 += xa.x * wa.x + xa.y * wa.y + xa.z * wa.z + xa.w * wa.w;
            float4 xb = *reinterpret_cast<const float4*>(&xs[s][r][d + 64]);
            float4 wb = *reinterpret_cast<const float4*>(&wrs[s][e][d + 64]);
            acc1 += xb.x * wb.x + xb.y * wb.y + xb.z * wb.z + xb.w * wb.w;
        }
        __syncthreads();
    }
    lg[r][e] = acc0 + acc1 + br[e];
    __syncthreads();

    if (tid < GR) {
        const int row = row0 + tid;
        float best = -1e30f; int bi = 0;
#pragma unroll
        for (int k = 0; k < E_SZ; k++) {
            float v = lg[tid][k];
            if (v > best) { best = v; bi = k; }
        }
        float sec = -1e30f; int si = 0;
#pragma unroll
        for (int k = 0; k < E_SZ; k++) {
            if (k == bi) continue;
            float v = lg[tid][k];
            if (v > sec) { sec = v; si = k; }
        }
        float t   = expf(sec - best);
        float inv = 1.0f / (1.0f + t);
        int p0 = atomicAdd(&g_cnt[bi], 1);
        g_rows[bi * B_SZ + p0] = row;  g_rw[bi * B_SZ + p0] = inv;
        int p1 = atomicAdd(&g_cnt[si], 1);
        g_rows[si * B_SZ + p1] = row;  g_rw[si * B_SZ + p1] = t * inv;
    }
}

// ---------------- kernel 3: mma.sync grouped gather-GEMM (R8, at its
// legacy-HMMA issue-rate roofline: ~264 TF/s of 272 ceiling) ----------------
extern __shared__ char dynsmem[];

__global__ __launch_bounds__(256, 1) void expert_gemm_mma(
    const float* __restrict__ x, const float* __restrict__ We,
    const float* __restrict__ be, float* __restrict__ out)
{
    const int e   = blockIdx.z;
    const int cnt = g_cnt[e];
    const int m0  = blockIdx.y * TM;
    if (m0 >= cnt) return;
    const int n0  = blockIdx.x * TN;

    __shared__ int   rs[TM];
    __shared__ float ws[TM];
    __shared__ float bes[TN];

    const int tid  = threadIdx.x;
    const int wid  = tid >> 5;
    const int lane = tid & 31;

    const uint32_t sb0 = smem_u32(dynsmem);

    for (int m = tid; m < TM; m += 256) {
        int gm = m0 + m; int rr = -1; float w = 0.0f;
        if (gm < cnt) { rr = g_rows[e * B_SZ + gm]; w = g_rw[e * B_SZ + gm]; }
        rs[m] = rr; ws[m] = w;
    }
    for (int j = tid; j < TN; j += 256) {
        int c = n0 + j;
        bes[j] = (c < C_SZ) ? be[e * C_SZ + c] : 0.0f;
    }
    __syncthreads();

    // ---- staging mappings ----
    const int am = tid >> 1;
    const int ak = (tid & 1) * 16;
    int arow = rs[am]; if (arow < 0) arow = 0;
    const float* __restrict__ xrow = x + (size_t)arow * D_SZ + ak;
    const uint32_t a_sts = (uint32_t)(am * ROWB + (ak >> 4) * 32);
    const int bn = tid;
    const bool bval = (n0 + bn) < C_SZ;
    const float* __restrict__ wcol =
        We + (size_t)e * D_SZ * C_SZ + (n0 + bn);
    const uint32_t b_sts = (uint32_t)(bn * ROWB);

    float areg[16], breg[32];

    auto ldg_a = [&](int c) {
        const int k0 = c * KC;
#pragma unroll
        for (int i = 0; i < 4; i++)
            *reinterpret_cast<float4*>(&areg[i * 4]) =
                *reinterpret_cast<const float4*>(xrow + k0 + i * 4);
    };
    auto ldg_b = [&](int c) {
        const int k0 = c * KC;
#pragma unroll
        for (int i = 0; i < 32; i++)
            breg[i] = bval ? wcol[(size_t)(k0 + i) * C_SZ] : 0.0f;
    };
    auto sts_a = [&](int s) {
        const uint32_t sb = sb0 + (uint32_t)s * STAGE_B;
        uint32_t h[8], l[8];
#pragma unroll
        for (int i = 0; i < 8; i++)
            split_pack(areg[2 * i], areg[2 * i + 1], h[i], l[i]);
        sts128(sb + OFF_AH + a_sts,      h[0], h[1], h[2], h[3]);
        sts128(sb + OFF_AH + a_sts + 16, h[4], h[5], h[6], h[7]);
        sts128(sb + OFF_AL + a_sts,      l[0], l[1], l[2], l[3]);
        sts128(sb + OFF_AL + a_sts + 16, l[4], l[5], l[6], l[7]);
    };
    auto sts_b = [&](int s) {
        const uint32_t sb = sb0 + (uint32_t)s * STAGE_B;
        uint32_t h[16], l[16];
#pragma unroll
        for (int i = 0; i < 16; i++)
            split_pack(breg[2 * i], breg[2 * i + 1], h[i], l[i]);
#pragma unroll
        for (int q = 0; q < 4; q++) {
            sts128(sb + OFF_BH + b_sts + q * 16,
                   h[4 * q], h[4 * q + 1], h[4 * q + 2], h[4 * q + 3]);
            sts128(sb + OFF_BL + b_sts + q * 16,
                   l[4 * q], l[4 * q + 1], l[4 * q + 2], l[4 * q + 3]);
        }
    };

    // ---- compute mappings: 2x4 warp grid, 64x64 warp tiles ----
    const int warp_m = (wid & 1) * 64;
    const int warp_n = (wid >> 1) * 64;
    const uint32_t a_lds =
        (uint32_t)((warp_m + (lane & 15)) * ROWB + (lane >> 4) * 16);
    const uint32_t b_lds =
        (uint32_t)((warp_n + ((lane >> 4) & 1) * 8 + (lane & 7)) * ROWB +
                   ((lane >> 3) & 1) * 16);

    float acc[4][8][4];
#pragma unroll
    for (int i = 0; i < 4; i++)
#pragma unroll
        for (int j = 0; j < 8; j++)
#pragma unroll
            for (int q = 0; q < 4; q++) acc[i][j][q] = 0.0f;

    auto compute_kk = [&](int s, int kk) {
        const uint32_t sb = sb0 + (uint32_t)s * STAGE_B;
        const uint32_t koff = (uint32_t)(kk * 32);
        uint32_t ah[4][4], al[4][4];
#pragma unroll
        for (int mt = 0; mt < 4; mt++) {
            LDSM4(ah[mt], sb + OFF_AH + a_lds + mt * (16 * ROWB) + koff);
            LDSM4(al[mt], sb + OFF_AL + a_lds + mt * (16 * ROWB) + koff);
        }
#pragma unroll
        for (int nh = 0; nh < 2; nh++) {
            uint32_t bh[2][4], bl[2][4];
#pragma unroll
            for (int np = 0; np < 2; np++) {
                const uint32_t ro = (uint32_t)((nh * 2 + np) * (16 * ROWB)) + koff;
                LDSM4(bh[np], sb + OFF_BH + b_lds + ro);
                LDSM4(bl[np], sb + OFF_BL + b_lds + ro);
            }
#pragma unroll
            for (int mt = 0; mt < 4; mt++)
#pragma unroll
                for (int nt2 = 0; nt2 < 4; nt2++) {
                    float* a4 = acc[mt][nh * 4 + nt2];
                    uint32_t* bhf = &bh[nt2 >> 1][(nt2 & 1) * 2];
                    uint32_t* blf = &bl[nt2 >> 1][(nt2 & 1) * 2];
                    MMA16816(a4, ah[mt], bhf[0], bhf[1]);
                    MMA16816(a4, ah[mt], blf[0], blf[1]);
                    MMA16816(a4, al[mt], bhf[0], bhf[1]);
                }
        }
    };

    // ---- main loop: staging interleaved into compute shadow ----
    ldg_a(0); ldg_b(0);
    sts_a(0); sts_b(0);
    __syncthreads();
    for (int c = 0; c < NCHUNK; c++) {
        const int s = c & 1;
        const bool more = (c + 1 < NCHUNK);
        if (more) ldg_a(c + 1);
        compute_kk(s, 0);
        if (more) { sts_a(s ^ 1); ldg_b(c + 1); }
        compute_kk(s, 1);
        if (more) sts_b(s ^ 1);
        __syncthreads();
    }

    // ---- epilogue: weighted atomic scatter ----
    const int gr = lane >> 2;
    const int gc = (lane & 3) * 2;
#pragma unroll
    for (int mt = 0; mt < 4; mt++) {
#pragma unroll
        for (int half = 0; half < 2; half++) {
            const int m = warp_m + mt * 16 + gr + half * 8;
            const int rr = rs[m];
            if (rr < 0) continue;
            const float w = ws[m];
            float* orow = out + (size_t)rr * C_SZ;
#pragma unroll
            for (int nt = 0; nt < 8; nt++) {
                const int cc = warp_n + nt * 8 + gc;
                const int c = n0 + cc;
                if (c >= C_SZ) continue;
                const float v0 = acc[mt][nt][half * 2 + 0];
                const float v1 = acc[mt][nt][half * 2 + 1];
                atomicAdd(orow + c,     w * (v0 + bes[cc]));
                atomicAdd(orow + c + 1, w * (v1 + bes[cc + 1]));
            }
        }
    }
}

// ---------------- launch ----------------
extern "C" void kernel_launch(void* const* d_in, const int* in_sizes, int n_in,
                              void* d_out, int out_size) {
    const float* x  = (const float*)d_in[0];
    const float* Wr = (const float*)d_in[1];
    const float* br = (const float*)d_in[2];
    const float* We = (const float*)d_in[3];
    const float* be = (const float*)d_in[4];
    float* out = (float*)d_out;

    cudaFuncSetAttribute(expert_gemm_mma,
                         cudaFuncAttributeMaxDynamicSharedMemorySize, DYN_BYTES);

    const int n4 = (B_SZ * C_SZ) / 4;
    zero_kernel<<<(n4 + 255) / 256, 256>>>((float4*)out, n4);
    gate_fused<<<B_SZ / GR, 256>>>(x, Wr, br);
    dim3 grid((C_SZ + TN - 1) / TN, B_SZ / TM, E_SZ);
    expert_gemm_mma<<<grid, 256, DYN_BYTES>>>(x, We, be, out);
}

// round 11
// speedup vs baseline: 1.1522x; 1.0009x over previous
#include <cuda_runtime.h>
#include <cuda_bf16.h>
#include <cstdint>

#define B_SZ 4096
#define D_SZ 2048
#define E_SZ 16
#define C_SZ 1000

#define TM 128
#define TN 256
#define KC 32
#define NCHUNK (D_SZ / KC)      // 64

// smem row = 32 bf16 = 64B, padded to 80B (5x16B -> ldmatrix conflict-free)
#define ROWB 80
#define A_TILE_B (128 * ROWB)   // 10240
#define B_TILE_B (256 * ROWB)   // 20480
#define OFF_AH 0
#define OFF_AL A_TILE_B
#define OFF_BH (2 * A_TILE_B)
#define OFF_BL (2 * A_TILE_B + B_TILE_B)
#define STAGE_B (2 * A_TILE_B + 2 * B_TILE_B)   // 61440
#define DYN_BYTES (2 * STAGE_B)                 // 122880

// gate split
#define GR 16
#define GP 4
#define DPG (D_SZ / GP)         // 512
#define GCH (DPG / 128)         // 4 chunks per partition

// ---------------- scratch ----------------
__device__ int   g_cnt[E_SZ];
__device__ int   g_rows[E_SZ * B_SZ];
__device__ float g_rw[E_SZ * B_SZ];
__device__ float g_part[GP][B_SZ][E_SZ];   // deterministic gate partials

// ---------------- helpers ----------------
__device__ __forceinline__ uint32_t smem_u32(const void* p) {
    uint32_t a;
    asm("{ .reg .u64 t; cvta.to.shared.u64 t, %1; cvt.u32.u64 %0, t; }"
        : "=r"(a) : "l"(p));
    return a;
}
__device__ __forceinline__ void split_pack(float a, float b, uint32_t& h, uint32_t& l) {
    __nv_bfloat162 hh = __floats2bfloat162_rn(a, b);
    float ra = a - __bfloat162float(hh.x);
    float rb = b - __bfloat162float(hh.y);
    __nv_bfloat162 ll = __floats2bfloat162_rn(ra, rb);
    h = *reinterpret_cast<uint32_t*>(&hh);
    l = *reinterpret_cast<uint32_t*>(&ll);
}
__device__ __forceinline__ void sts128(uint32_t addr, uint32_t a, uint32_t b,
                                       uint32_t c, uint32_t d) {
    asm volatile("st.shared.v4.b32 [%0], {%1,%2,%3,%4};"
                 :: "r"(addr), "r"(a), "r"(b), "r"(c), "r"(d) : "memory");
}
__device__ __forceinline__ void cpa16(uint32_t dst, const void* src) {
    asm volatile("cp.async.ca.shared.global [%0], [%1], 16;"
                 :: "r"(dst), "l"(src));
}
#define CP_COMMIT() asm volatile("cp.async.commit_group;" ::: "memory")
#define CP_WAIT1()  asm volatile("cp.async.wait_group 1;" ::: "memory")
#define CP_WAIT0()  asm volatile("cp.async.wait_group 0;" ::: "memory")
#define LDSM4(r, addr)                                                        \
    asm volatile("ldmatrix.sync.aligned.m8n8.x4.shared.b16 {%0,%1,%2,%3}, [%4];" \
                 : "=r"((r)[0]), "=r"((r)[1]), "=r"((r)[2]), "=r"((r)[3])     \
                 : "r"(addr))
#define MMA16816(c, a, b0, b1)                                                \
    asm volatile("mma.sync.aligned.m16n8k16.row.col.f32.bf16.bf16.f32 "       \
                 "{%0,%1,%2,%3}, {%4,%5,%6,%7}, {%8,%9}, {%0,%1,%2,%3};"      \
                 : "+f"((c)[0]), "+f"((c)[1]), "+f"((c)[2]), "+f"((c)[3])     \
                 : "r"((a)[0]), "r"((a)[1]), "r"((a)[2]), "r"((a)[3]),        \
                   "r"(b0), "r"(b1))

// ---------------- kernel 1: zero output + expert counts ----------------
__global__ void zero_kernel(float4* __restrict__ out, int n4) {
    int i = blockIdx.x * blockDim.x + threadIdx.x;
    if (i < n4) out[i] = make_float4(0.f, 0.f, 0.f, 0.f);
    if (i < E_SZ) g_cnt[i] = 0;
}

// ---------------- kernel 2: gate partials (split-D for 4x MLP) -------------
// grid (B_SZ/GR, GP): 1024 blocks nearly all resident -> x read runs at
// bandwidth, not latency (R9/R10 gates measured 0.5-0.8 TB/s; this exposes 4x
// the outstanding loads). Partials are written to fixed slots -> deterministic.
__global__ __launch_bounds__(256) void gate_part(
    const float* __restrict__ x, const float* __restrict__ Wr)
{
    __shared__ __align__(16) float xs[2][GR][132];
    __shared__ __align__(16) float wrs[2][E_SZ][132];

    const int tid   = threadIdx.x;
    const int row0  = blockIdx.x * GR;
    const int dbase = blockIdx.y * DPG;
    const int e     = tid & 15;
    const int r     = tid >> 4;

    const int xrow = tid >> 4;
    const int xseg = tid & 15;
    const float* xsrc = x + (size_t)(row0 + xrow) * D_SZ + dbase;
    const int wd = tid >> 1;
    const int we = (tid & 1) * 8;

    float4 wr0, wr1;
    auto ldg_wr = [&](int ch) {
        const float* p = Wr + (size_t)(dbase + ch * 128 + wd) * E_SZ + we;
        wr0 = *reinterpret_cast<const float4*>(p);
        wr1 = *reinterpret_cast<const float4*>(p + 4);
    };
    auto sts_wr = [&](int s) {
        wrs[s][we + 0][wd] = wr0.x; wrs[s][we + 1][wd] = wr0.y;
        wrs[s][we + 2][wd] = wr0.z; wrs[s][we + 3][wd] = wr0.w;
        wrs[s][we + 4][wd] = wr1.x; wrs[s][we + 5][wd] = wr1.y;
        wrs[s][we + 6][wd] = wr1.z; wrs[s][we + 7][wd] = wr1.w;
    };
    auto cpa_xs = [&](int ch, int s) {
        const int d0 = ch * 128;
        cpa16(smem_u32(&xs[s][xrow][xseg * 4]),        xsrc + d0 + xseg * 4);
        cpa16(smem_u32(&xs[s][xrow][(xseg + 16) * 4]), xsrc + d0 + (xseg + 16) * 4);
    };

    float acc0 = 0.0f, acc1 = 0.0f;

    ldg_wr(0);
    cpa_xs(0, 0); CP_COMMIT();
    for (int ch = 0; ch < GCH; ch++) {
        const int s = ch & 1;
        sts_wr(s);
        if (ch + 1 < GCH) {
            ldg_wr(ch + 1);
            cpa_xs(ch + 1, s ^ 1); CP_COMMIT();
            CP_WAIT1();
        } else {
            CP_WAIT0();
        }
        __syncthreads();
#pragma unroll
        for (int d = 0; d < 64; d += 4) {
            float4 xa = *reinterpret_cast<const float4*>(&xs[s][r][d]);
            float4 wa = *reinterpret_cast<const float4*>(&wrs[s][e][d]);
            acc0 += xa.x * wa.x + xa.y * wa.y + xa.z * wa.z + xa.w * wa.w;
            float4 xb = *reinterpret_cast<const float4*>(&xs[s][r][d + 64]);
            float4 wb = *reinterpret_cast<const float4*>(&wrs[s][e][d + 64]);
            acc1 += xb.x * wb.x + xb.y * wb.y + xb.z * wb.z + xb.w * wb.w;
        }
        __syncthreads();
    }
    g_part[blockIdx.y][row0 + r][e] = acc0 + acc1;
}

// ---------------- kernel 3: reduce partials + top-2 softmax + bucket -------
__global__ __launch_bounds__(256) void gate_reduce(const float* __restrict__ br) {
    const int row = blockIdx.x * 256 + threadIdx.x;
    if (row >= B_SZ) return;

    float lg[E_SZ];
#pragma unroll
    for (int q = 0; q < 4; q++) {
        float4 s = make_float4(0.f, 0.f, 0.f, 0.f);
#pragma unroll
        for (int p = 0; p < GP; p++) {        // fixed order -> deterministic
            float4 v = *reinterpret_cast<const float4*>(&g_part[p][row][q * 4]);
            s.x += v.x; s.y += v.y; s.z += v.z; s.w += v.w;
        }
        lg[q * 4 + 0] = s.x + br[q * 4 + 0];
        lg[q * 4 + 1] = s.y + br[q * 4 + 1];
        lg[q * 4 + 2] = s.z + br[q * 4 + 2];
        lg[q * 4 + 3] = s.w + br[q * 4 + 3];
    }

    float best = -1e30f; int bi = 0;
#pragma unroll
    for (int k = 0; k < E_SZ; k++)
        if (lg[k] > best) { best = lg[k]; bi = k; }
    float sec = -1e30f; int si = 0;
#pragma unroll
    for (int k = 0; k < E_SZ; k++) {
        if (k == bi) continue;
        if (lg[k] > sec) { sec = lg[k]; si = k; }
    }
    float t   = expf(sec - best);
    float inv = 1.0f / (1.0f + t);
    int p0 = atomicAdd(&g_cnt[bi], 1);
    g_rows[bi * B_SZ + p0] = row;  g_rw[bi * B_SZ + p0] = inv;
    int p1 = atomicAdd(&g_cnt[si], 1);
    g_rows[si * B_SZ + p1] = row;  g_rw[si * B_SZ + p1] = t * inv;
}

// ---------------- kernel 4: mma.sync grouped gather-GEMM (unchanged R8;
// at the legacy-HMMA issue-rate ceiling) ------------------------------------
extern __shared__ char dynsmem[];

__global__ __launch_bounds__(256, 1) void expert_gemm_mma(
    const float* __restrict__ x, const float* __restrict__ We,
    const float* __restrict__ be, float* __restrict__ out)
{
    const int e   = blockIdx.z;
    const int cnt = g_cnt[e];
    const int m0  = blockIdx.y * TM;
    if (m0 >= cnt) return;
    const int n0  = blockIdx.x * TN;

    __shared__ int   rs[TM];
    __shared__ float ws[TM];
    __shared__ float bes[TN];

    const int tid  = threadIdx.x;
    const int wid  = tid >> 5;
    const int lane = tid & 31;

    const uint32_t sb0 = smem_u32(dynsmem);

    for (int m = tid; m < TM; m += 256) {
        int gm = m0 + m; int rr = -1; float w = 0.0f;
        if (gm < cnt) { rr = g_rows[e * B_SZ + gm]; w = g_rw[e * B_SZ + gm]; }
        rs[m] = rr; ws[m] = w;
    }
    for (int j = tid; j < TN; j += 256) {
        int c = n0 + j;
        bes[j] = (c < C_SZ) ? be[e * C_SZ + c] : 0.0f;
    }
    __syncthreads();

    // ---- staging mappings ----
    const int am = tid >> 1;
    const int ak = (tid & 1) * 16;
    int arow = rs[am]; if (arow < 0) arow = 0;
    const float* __restrict__ xrow = x + (size_t)arow * D_SZ + ak;
    const uint32_t a_sts = (uint32_t)(am * ROWB + (ak >> 4) * 32);
    const int bn = tid;
    const bool bval = (n0 + bn) < C_SZ;
    const float* __restrict__ wcol =
        We + (size_t)e * D_SZ * C_SZ + (n0 + bn);
    const uint32_t b_sts = (uint32_t)(bn * ROWB);

    float areg[16], breg[32];

    auto ldg_a = [&](int c) {
        const int k0 = c * KC;
#pragma unroll
        for (int i = 0; i < 4; i++)
            *reinterpret_cast<float4*>(&areg[i * 4]) =
                *reinterpret_cast<const float4*>(xrow + k0 + i * 4);
    };
    auto ldg_b = [&](int c) {
        const int k0 = c * KC;
#pragma unroll
        for (int i = 0; i < 32; i++)
            breg[i] = bval ? wcol[(size_t)(k0 + i) * C_SZ] : 0.0f;
    };
    auto sts_a = [&](int s) {
        const uint32_t sb = sb0 + (uint32_t)s * STAGE_B;
        uint32_t h[8], l[8];
#pragma unroll
        for (int i = 0; i < 8; i++)
            split_pack(areg[2 * i], areg[2 * i + 1], h[i], l[i]);
        sts128(sb + OFF_AH + a_sts,      h[0], h[1], h[2], h[3]);
        sts128(sb + OFF_AH + a_sts + 16, h[4], h[5], h[6], h[7]);
        sts128(sb + OFF_AL + a_sts,      l[0], l[1], l[2], l[3]);
        sts128(sb + OFF_AL + a_sts + 16, l[4], l[5], l[6], l[7]);
    };
    auto sts_b = [&](int s) {
        const uint32_t sb = sb0 + (uint32_t)s * STAGE_B;
        uint32_t h[16], l[16];
#pragma unroll
        for (int i = 0; i < 16; i++)
            split_pack(breg[2 * i], breg[2 * i + 1], h[i], l[i]);
#pragma unroll
        for (int q = 0; q < 4; q++) {
            sts128(sb + OFF_BH + b_sts + q * 16,
                   h[4 * q], h[4 * q + 1], h[4 * q + 2], h[4 * q + 3]);
            sts128(sb + OFF_BL + b_sts + q * 16,
                   l[4 * q], l[4 * q + 1], l[4 * q + 2], l[4 * q + 3]);
        }
    };

    // ---- compute mappings: 2x4 warp grid, 64x64 warp tiles ----
    const int warp_m = (wid & 1) * 64;
    const int warp_n = (wid >> 1) * 64;
    const uint32_t a_lds =
        (uint32_t)((warp_m + (lane & 15)) * ROWB + (lane >> 4) * 16);
    const uint32_t b_lds =
        (uint32_t)((warp_n + ((lane >> 4) & 1) * 8 + (lane & 7)) * ROWB +
                   ((lane >> 3) & 1) * 16);

    float acc[4][8][4];
#pragma unroll
    for (int i = 0; i < 4; i++)
#pragma unroll
        for (int j = 0; j < 8; j++)
#pragma unroll
            for (int q = 0; q < 4; q++) acc[i][j][q] = 0.0f;

    auto compute_kk = [&](int s, int kk) {
        const uint32_t sb = sb0 + (uint32_t)s * STAGE_B;
        const uint32_t koff = (uint32_t)(kk * 32);
        uint32_t ah[4][4], al[4][4];
#pragma unroll
        for (int mt = 0; mt < 4; mt++) {
            LDSM4(ah[mt], sb + OFF_AH + a_lds + mt * (16 * ROWB) + koff);
            LDSM4(al[mt], sb + OFF_AL + a_lds + mt * (16 * ROWB) + koff);
        }
#pragma unroll
        for (int nh = 0; nh < 2; nh++) {
            uint32_t bh[2][4], bl[2][4];
#pragma unroll
            for (int np = 0; np < 2; np++) {
                const uint32_t ro = (uint32_t)((nh * 2 + np) * (16 * ROWB)) + koff;
                LDSM4(bh[np], sb + OFF_BH + b_lds + ro);
                LDSM4(bl[np], sb + OFF_BL + b_lds + ro);
            }
#pragma unroll
            for (int mt = 0; mt < 4; mt++)
#pragma unroll
                for (int nt2 = 0; nt2 < 4; nt2++) {
                    float* a4 = acc[mt][nh * 4 + nt2];
                    uint32_t* bhf = &bh[nt2 >> 1][(nt2 & 1) * 2];
                    uint32_t* blf = &bl[nt2 >> 1][(nt2 & 1) * 2];
                    MMA16816(a4, ah[mt], bhf[0], bhf[1]);
                    MMA16816(a4, ah[mt], blf[0], blf[1]);
                    MMA16816(a4, al[mt], bhf[0], bhf[1]);
                }
        }
    };

    // ---- main loop: staging interleaved into compute shadow ----
    ldg_a(0); ldg_b(0);
    sts_a(0); sts_b(0);
    __syncthreads();
    for (int c = 0; c < NCHUNK; c++) {
        const int s = c & 1;
        const bool more = (c + 1 < NCHUNK);
        if (more) ldg_a(c + 1);
        compute_kk(s, 0);
        if (more) { sts_a(s ^ 1); ldg_b(c + 1); }
        compute_kk(s, 1);
        if (more) sts_b(s ^ 1);
        __syncthreads();
    }

    // ---- epilogue: weighted atomic scatter ----
    const int gr = lane >> 2;
    const int gc = (lane & 3) * 2;
#pragma unroll
    for (int mt = 0; mt < 4; mt++) {
#pragma unroll
        for (int half = 0; half < 2; half++) {
            const int m = warp_m + mt * 16 + gr + half * 8;
            const int rr = rs[m];
            if (rr < 0) continue;
            const float w = ws[m];
            float* orow = out + (size_t)rr * C_SZ;
#pragma unroll
            for (int nt = 0; nt < 8; nt++) {
                const int cc = warp_n + nt * 8 + gc;
                const int c = n0 + cc;
                if (c >= C_SZ) continue;
                const float v0 = acc[mt][nt][half * 2 + 0];
                const float v1 = acc[mt][nt][half * 2 + 1];
                atomicAdd(orow + c,     w * (v0 + bes[cc]));
                atomicAdd(orow + c + 1, w * (v1 + bes[cc + 1]));
            }
        }
    }
}

// ---------------- launch ----------------
extern "C" void kernel_launch(void* const* d_in, const int* in_sizes, int n_in,
                              void* d_out, int out_size) {
    const float* x  = (const float*)d_in[0];
    const float* Wr = (const float*)d_in[1];
    const float* br = (const float*)d_in[2];
    const float* We = (const float*)d_in[3];
    const float* be = (const float*)d_in[4];
    float* out = (float*)d_out;

    cudaFuncSetAttribute(expert_gemm_mma,
                         cudaFuncAttributeMaxDynamicSharedMemorySize, DYN_BYTES);

    const int n4 = (B_SZ * C_SZ) / 4;
    zero_kernel<<<(n4 + 255) / 256, 256>>>((float4*)out, n4);
    dim3 ggrid(B_SZ / GR, GP);
    gate_part<<<ggrid, 256>>>(x, Wr);
    gate_reduce<<<B_SZ / 256, 256>>>(br);
    dim3 grid((C_SZ + TN - 1) / TN, B_SZ / TM, E_SZ);
    expert_gemm_mma<<<grid, 256, DYN_BYTES>>>(x, We, be, out);
}

// round 12
// speedup vs baseline: 1.1906x; 1.0333x over previous
#include <cuda_runtime.h>
#include <cuda_bf16.h>
#include <cstdint>

#define B_SZ 4096
#define D_SZ 2048
#define E_SZ 16
#define C_SZ 1000
#define NPAD 1024

#define TM 128
#define TN 256
#define KC 32
#define NCHUNK (D_SZ / KC)      // 64

// A smem: [m][k] rows of 64B padded to 80B (ldmatrix conflict-free)
#define ROWB 80
#define A_TILE_B (128 * ROWB)               // 10240
// B smem: [k][n] rows of 512B padded to 528B (33 segs -> trans conflict-free)
#define BROWB 528
#define B_TILE_B (KC * BROWB)               // 16896
#define OFF_AH 0
#define OFF_AL A_TILE_B
#define OFF_BH (2 * A_TILE_B)
#define OFF_BL (2 * A_TILE_B + B_TILE_B)
#define STAGE_B (2 * A_TILE_B + 2 * B_TILE_B)   // 54272
#define NST 3
#define DYN_BYTES (NST * STAGE_B)               // 162816

// gate split
#define GR 16
#define GP 4
#define DPG (D_SZ / GP)
#define GCH (DPG / 128)

// ---------------- scratch ----------------
__device__ int   g_cnt[E_SZ];
__device__ int   g_rows[E_SZ * B_SZ];
__device__ float g_rw[E_SZ * B_SZ];
__device__ float g_part[GP][B_SZ][E_SZ];
__device__ __nv_bfloat16 x_h[(size_t)B_SZ * D_SZ];
__device__ __nv_bfloat16 x_l[(size_t)B_SZ * D_SZ];
__device__ __nv_bfloat16 w_h[(size_t)E_SZ * D_SZ * NPAD];  // [e][k][n]
__device__ __nv_bfloat16 w_l[(size_t)E_SZ * D_SZ * NPAD];

// ---------------- helpers ----------------
__device__ __forceinline__ uint32_t smem_u32(const void* p) {
    uint32_t a;
    asm("{ .reg .u64 t; cvta.to.shared.u64 t, %1; cvt.u32.u64 %0, t; }"
        : "=r"(a) : "l"(p));
    return a;
}
__device__ __forceinline__ void split_pack(float a, float b, uint32_t& h, uint32_t& l) {
    __nv_bfloat162 hh = __floats2bfloat162_rn(a, b);
    float ra = a - __bfloat162float(hh.x);
    float rb = b - __bfloat162float(hh.y);
    __nv_bfloat162 ll = __floats2bfloat162_rn(ra, rb);
    h = *reinterpret_cast<uint32_t*>(&hh);
    l = *reinterpret_cast<uint32_t*>(&ll);
}
__device__ __forceinline__ void cpa16(uint32_t dst, const void* src) {
    asm volatile("cp.async.ca.shared.global [%0], [%1], 16;"
                 :: "r"(dst), "l"(src));
}
#define CP_COMMIT() asm volatile("cp.async.commit_group;" ::: "memory")
#define CP_WAITN(n) asm volatile("cp.async.wait_group %0;" :: "n"(n) : "memory")
#define LDSM4(r, addr)                                                        \
    asm volatile("ldmatrix.sync.aligned.m8n8.x4.shared.b16 {%0,%1,%2,%3}, [%4];" \
                 : "=r"((r)[0]), "=r"((r)[1]), "=r"((r)[2]), "=r"((r)[3])     \
                 : "r"(addr))
#define LDSM4T(r, addr)                                                       \
    asm volatile("ldmatrix.sync.aligned.m8n8.x4.trans.shared.b16 {%0,%1,%2,%3}, [%4];" \
                 : "=r"((r)[0]), "=r"((r)[1]), "=r"((r)[2]), "=r"((r)[3])     \
                 : "r"(addr))
#define MMA16816(c, a, b0, b1)                                                \
    asm volatile("mma.sync.aligned.m16n8k16.row.col.f32.bf16.bf16.f32 "       \
                 "{%0,%1,%2,%3}, {%4,%5,%6,%7}, {%8,%9}, {%0,%1,%2,%3};"      \
                 : "+f"((c)[0]), "+f"((c)[1]), "+f"((c)[2]), "+f"((c)[3])     \
                 : "r"((a)[0]), "r"((a)[1]), "r"((a)[2]), "r"((a)[3]),        \
                   "r"(b0), "r"(b1))

// ---------------- kernel 1: zero output + expert counts ----------------
__global__ void zero_kernel(float4* __restrict__ out, int n4) {
    int i = blockIdx.x * blockDim.x + threadIdx.x;
    if (i < n4) out[i] = make_float4(0.f, 0.f, 0.f, 0.f);
    if (i < E_SZ) g_cnt[i] = 0;
}

// ---------------- kernel 2: convert x -> bf16 hi/lo (stream) ---------------
__global__ void conv_x(const float4* __restrict__ xin, int n4) {
    int i = blockIdx.x * blockDim.x + threadIdx.x;
    if (i >= n4) return;
    float4 v = xin[i];
    uint32_t h0, l0, h1, l1;
    split_pack(v.x, v.y, h0, l0);
    split_pack(v.z, v.w, h1, l1);
    reinterpret_cast<uint2*>(x_h)[i] = make_uint2(h0, h1);
    reinterpret_cast<uint2*>(x_l)[i] = make_uint2(l0, l1);
}

// ---------------- kernel 3: convert We -> bf16 hi/lo, same [e][k][n] layout,
// n padded 1000->1024 with zeros. Pure stream (no transpose). ----------------
__global__ __launch_bounds__(256) void conv_w(const float* __restrict__ We) {
    const size_t row = blockIdx.x;              // e*D_SZ + k, 32768 rows
    const int t = threadIdx.x;
    const float* src = We + row * C_SZ;
    uint2* dh = reinterpret_cast<uint2*>(w_h + row * NPAD);
    uint2* dl = reinterpret_cast<uint2*>(w_l + row * NPAD);
    if (t < 250) {
        float4 v = *reinterpret_cast<const float4*>(src + 4 * t);
        uint32_t h0, l0, h1, l1;
        split_pack(v.x, v.y, h0, l0);
        split_pack(v.z, v.w, h1, l1);
        dh[t] = make_uint2(h0, h1);
        dl[t] = make_uint2(l0, l1);
    } else {
        dh[t] = make_uint2(0u, 0u);
        dl[t] = make_uint2(0u, 0u);
    }
}

// ---------------- kernel 4: gate partials (split-D) ----------------
__global__ __launch_bounds__(256) void gate_part(
    const float* __restrict__ x, const float* __restrict__ Wr)
{
    __shared__ __align__(16) float xs[2][GR][132];
    __shared__ __align__(16) float wrs[2][E_SZ][132];

    const int tid   = threadIdx.x;
    const int row0  = blockIdx.x * GR;
    const int dbase = blockIdx.y * DPG;
    const int e     = tid & 15;
    const int r     = tid >> 4;

    const int xrow = tid >> 4;
    const int xseg = tid & 15;
    const float* xsrc = x + (size_t)(row0 + xrow) * D_SZ + dbase;
    const int wd = tid >> 1;
    const int we = (tid & 1) * 8;

    float4 wr0, wr1;
    auto ldg_wr = [&](int ch) {
        const float* p = Wr + (size_t)(dbase + ch * 128 + wd) * E_SZ + we;
        wr0 = *reinterpret_cast<const float4*>(p);
        wr1 = *reinterpret_cast<const float4*>(p + 4);
    };
    auto sts_wr = [&](int s) {
        wrs[s][we + 0][wd] = wr0.x; wrs[s][we + 1][wd] = wr0.y;
        wrs[s][we + 2][wd] = wr0.z; wrs[s][we + 3][wd] = wr0.w;
        wrs[s][we + 4][wd] = wr1.x; wrs[s][we + 5][wd] = wr1.y;
        wrs[s][we + 6][wd] = wr1.z; wrs[s][we + 7][wd] = wr1.w;
    };
    auto cpa_xs = [&](int ch, int s) {
        const int d0 = ch * 128;
        cpa16(smem_u32(&xs[s][xrow][xseg * 4]),        xsrc + d0 + xseg * 4);
        cpa16(smem_u32(&xs[s][xrow][(xseg + 16) * 4]), xsrc + d0 + (xseg + 16) * 4);
    };

    float acc0 = 0.0f, acc1 = 0.0f;

    ldg_wr(0);
    cpa_xs(0, 0); CP_COMMIT();
    for (int ch = 0; ch < GCH; ch++) {
        const int s = ch & 1;
        sts_wr(s);
        if (ch + 1 < GCH) {
            ldg_wr(ch + 1);
            cpa_xs(ch + 1, s ^ 1); CP_COMMIT();
            CP_WAITN(1);
        } else {
            CP_WAITN(0);
        }
        __syncthreads();
#pragma unroll
        for (int d = 0; d < 64; d += 4) {
            float4 xa = *reinterpret_cast<const float4*>(&xs[s][r][d]);
            float4 wa = *reinterpret_cast<const float4*>(&wrs[s][e][d]);
            acc0 += xa.x * wa.x + xa.y * wa.y + xa.z * wa.z + xa.w * wa.w;
            float4 xb = *reinterpret_cast<const float4*>(&xs[s][r][d + 64]);
            float4 wb = *reinterpret_cast<const float4*>(&wrs[s][e][d + 64]);
            acc1 += xb.x * wb.x + xb.y * wb.y + xb.z * wb.z + xb.w * wb.w;
        }
        __syncthreads();
    }
    g_part[blockIdx.y][row0 + r][e] = acc0 + acc1;
}

// ---------------- kernel 5: reduce partials + top-2 softmax + bucket -------
__global__ __launch_bounds__(256) void gate_reduce(const float* __restrict__ br) {
    const int row = blockIdx.x * 256 + threadIdx.x;
    if (row >= B_SZ) return;

    float lg[E_SZ];
#pragma unroll
    for (int q = 0; q < 4; q++) {
        float4 s = make_float4(0.f, 0.f, 0.f, 0.f);
#pragma unroll
        for (int p = 0; p < GP; p++) {
            float4 v = *reinterpret_cast<const float4*>(&g_part[p][row][q * 4]);
            s.x += v.x; s.y += v.y; s.z += v.z; s.w += v.w;
        }
        lg[q * 4 + 0] = s.x + br[q * 4 + 0];
        lg[q * 4 + 1] = s.y + br[q * 4 + 1];
        lg[q * 4 + 2] = s.z + br[q * 4 + 2];
        lg[q * 4 + 3] = s.w + br[q * 4 + 3];
    }

    float best = -1e30f; int bi = 0;
#pragma unroll
    for (int k = 0; k < E_SZ; k++)
        if (lg[k] > best) { best = lg[k]; bi = k; }
    float sec = -1e30f; int si = 0;
#pragma unroll
    for (int k = 0; k < E_SZ; k++) {
        if (k == bi) continue;
        if (lg[k] > sec) { sec = lg[k]; si = k; }
    }
    float t   = expf(sec - best);
    float inv = 1.0f / (1.0f + t);
    int p0 = atomicAdd(&g_cnt[bi], 1);
    g_rows[bi * B_SZ + p0] = row;  g_rw[bi * B_SZ + p0] = inv;
    int p1 = atomicAdd(&g_cnt[si], 1);
    g_rows[si * B_SZ + p1] = row;  g_rw[si * B_SZ + p1] = t * inv;
}

// ---------------- kernel 6: 3-stage cp.async mma.sync gather-GEMM ----------
extern __shared__ char dynsmem[];

__global__ __launch_bounds__(256, 1) void expert_gemm_mma(
    const float* __restrict__ be, float* __restrict__ out)
{
    const int e   = blockIdx.z;
    const int cnt = g_cnt[e];
    const int m0  = blockIdx.y * TM;
    if (m0 >= cnt) return;
    const int n0  = blockIdx.x * TN;

    __shared__ int   rs[TM];
    __shared__ float ws[TM];
    __shared__ float bes[TN];

    const int tid  = threadIdx.x;
    const int wid  = tid >> 5;
    const int lane = tid & 31;

    const uint32_t sb0 = smem_u32(dynsmem);

    for (int m = tid; m < TM; m += 256) {
        int gm = m0 + m; int rr = -1; float w = 0.0f;
        if (gm < cnt) { rr = g_rows[e * B_SZ + gm]; w = g_rw[e * B_SZ + gm]; }
        rs[m] = rr; ws[m] = w;
    }
    for (int j = tid; j < TN; j += 256) {
        int c = n0 + j;
        bes[j] = (c < C_SZ) ? be[e * C_SZ + c] : 0.0f;
    }
    __syncthreads();

    // ---- cp.async mappings: 12 x 16B per thread per chunk ----
    // A: thread -> row am = tid>>1, k-half t2 = tid&1 (two 16B segs)
    const int am = tid >> 1;
    const int t2 = tid & 1;
    int ra = rs[am]; if (ra < 0) ra = 0;
    const __nv_bfloat16* srcAh = x_h + (size_t)ra * D_SZ + t2 * 16;
    const __nv_bfloat16* srcAl = x_l + (size_t)ra * D_SZ + t2 * 16;
    const uint32_t aoff = (uint32_t)(am * ROWB + t2 * 32);
    // B: thread -> k-row kr = tid>>3, n-seg base ns = (tid&7)*4 (4 segs)
    const int kr = tid >> 3;
    const int ns = (tid & 7) * 4;
    const __nv_bfloat16* srcBh =
        w_h + ((size_t)e * D_SZ + kr) * NPAD + n0 + ns * 8;
    const __nv_bfloat16* srcBl =
        w_l + ((size_t)e * D_SZ + kr) * NPAD + n0 + ns * 8;
    const uint32_t boff = (uint32_t)(kr * BROWB + ns * 16);

    auto issue_stage = [&](int c, int slot) {
        const uint32_t sb = sb0 + (uint32_t)slot * STAGE_B;
        const int ko = c * KC;                       // element offset in k
        cpa16(sb + OFF_AH + aoff,      srcAh + ko);
        cpa16(sb + OFF_AH + aoff + 16, srcAh + ko + 8);
        cpa16(sb + OFF_AL + aoff,      srcAl + ko);
        cpa16(sb + OFF_AL + aoff + 16, srcAl + ko + 8);
        const size_t bko = (size_t)ko * NPAD;
#pragma unroll
        for (int j = 0; j < 4; j++) {
            cpa16(sb + OFF_BH + boff + j * 16, srcBh + bko + j * 8);
            cpa16(sb + OFF_BL + boff + j * 16, srcBl + bko + j * 8);
        }
        CP_COMMIT();
    };

    // ---- compute mappings: 2x4 warp grid, 64x64 warp tiles ----
    const int warp_m = (wid & 1) * 64;
    const int warp_n = (wid >> 1) * 64;
    const uint32_t a_lds =
        (uint32_t)((warp_m + (lane & 15)) * ROWB + (lane >> 4) * 16);
    // trans-B lane map: k-row = lane&15, n-half = (lane>>4)&1
    const uint32_t b_lds =
        (uint32_t)((lane & 15) * BROWB + ((lane >> 4) & 1) * 16 + warp_n * 2);

    float acc[4][8][4];
#pragma unroll
    for (int i = 0; i < 4; i++)
#pragma unroll
        for (int j = 0; j < 8; j++)
#pragma unroll
            for (int q = 0; q < 4; q++) acc[i][j][q] = 0.0f;

    auto compute_chunk = [&](int slot) {
        const uint32_t sb = sb0 + (uint32_t)slot * STAGE_B;
        // A fragments for both kk halves, loaded once
        uint32_t ah[2][4][4], al[2][4][4];
#pragma unroll
        for (int kk = 0; kk < 2; kk++)
#pragma unroll
            for (int mt = 0; mt < 4; mt++) {
                const uint32_t ao = a_lds + mt * (16 * ROWB) + kk * 32;
                LDSM4(ah[kk][mt], sb + OFF_AH + ao);
                LDSM4(al[kk][mt], sb + OFF_AL + ao);
            }
        // B groups g = kk*2 + nh, double-buffered one group ahead
        uint32_t bh[2][2][4], bl[2][2][4];
        auto load_b = [&](int g, int buf) {
            const int kk = g >> 1, nh = g & 1;
            const uint32_t base = sb + b_lds + kk * (16 * BROWB);
#pragma unroll
            for (int np = 0; np < 2; np++) {
                const uint32_t no = (uint32_t)((nh * 32 + np * 16) * 2);
                LDSM4T(bh[buf][np], base + OFF_BH + no);
                LDSM4T(bl[buf][np], base + OFF_BL + no);
            }
        };
        load_b(0, 0);
#pragma unroll
        for (int g = 0; g < 4; g++) {
            const int buf = g & 1;
            if (g < 3) load_b(g + 1, buf ^ 1);
            const int kk = g >> 1, nh = g & 1;
#pragma unroll
            for (int mt = 0; mt < 4; mt++)
#pragma unroll
                for (int np = 0; np < 2; np++)
#pragma unroll
                    for (int nt = 0; nt < 2; nt++) {
                        float* a4 = acc[mt][nh * 4 + np * 2 + nt];
                        uint32_t* bhf = &bh[buf][np][nt * 2];
                        uint32_t* blf = &bl[buf][np][nt * 2];
                        MMA16816(a4, ah[kk][mt], bhf[0], bhf[1]);
                        MMA16816(a4, ah[kk][mt], blf[0], blf[1]);
                        MMA16816(a4, al[kk][mt], bhf[0], bhf[1]);
                    }
        }
    };

    // ---- main loop: 3-stage pipeline ----
    issue_stage(0, 0);
    issue_stage(1, 1);
    for (int c = 0; c < NCHUNK; c++) {
        const int slot = c % NST;
        if (c + 2 < NCHUNK) {
            issue_stage(c + 2, (c + 2) % NST);
            CP_WAITN(2);
        } else if (c + 1 < NCHUNK) {
            CP_WAITN(1);
        } else {
            CP_WAITN(0);
        }
        __syncthreads();
        compute_chunk(slot);
        __syncthreads();
    }

    // ---- epilogue: weighted atomic scatter ----
    const int gr = lane >> 2;
    const int gc = (lane & 3) * 2;
#pragma unroll
    for (int mt = 0; mt < 4; mt++) {
#pragma unroll
        for (int half = 0; half < 2; half++) {
            const int m = warp_m + mt * 16 + gr + half * 8;
            const int rr = rs[m];
            if (rr < 0) continue;
            const float w = ws[m];
            float* orow = out + (size_t)rr * C_SZ;
#pragma unroll
            for (int nt = 0; nt < 8; nt++) {
                const int cc = warp_n + nt * 8 + gc;
                const int c = n0 + cc;
                if (c >= C_SZ) continue;
                const float v0 = acc[mt][nt][half * 2 + 0];
                const float v1 = acc[mt][nt][half * 2 + 1];
                atomicAdd(orow + c,     w * (v0 + bes[cc]));
                atomicAdd(orow + c + 1, w * (v1 + bes[cc + 1]));
            }
        }
    }
}

// ---------------- launch ----------------
extern "C" void kernel_launch(void* const* d_in, const int* in_sizes, int n_in,
                              void* d_out, int out_size) {
    const float* x  = (const float*)d_in[0];
    const float* Wr = (const float*)d_in[1];
    const float* br = (const float*)d_in[2];
    const float* We = (const float*)d_in[3];
    const float* be = (const float*)d_in[4];
    float* out = (float*)d_out;

    cudaFuncSetAttribute(expert_gemm_mma,
                         cudaFuncAttributeMaxDynamicSharedMemorySize, DYN_BYTES);

    const int n4 = (B_SZ * C_SZ) / 4;
    zero_kernel<<<(n4 + 255) / 256, 256>>>((float4*)out, n4);
    const int nx4 = (B_SZ * D_SZ) / 4;
    conv_x<<<(nx4 + 255) / 256, 256>>>((const float4*)x, nx4);
    conv_w<<<E_SZ * D_SZ, 256>>>(We);
    dim3 ggrid(B_SZ / GR, GP);
    gate_part<<<ggrid, 256>>>(x, Wr);
    gate_reduce<<<B_SZ / 256, 256>>>(br);
    dim3 grid((C_SZ + TN - 1) / TN, B_SZ / TM, E_SZ);
    expert_gemm_mma<<<grid, 256, DYN_BYTES>>>(be, out);
}

// round 13
// speedup vs baseline: 1.2556x; 1.0545x over previous
#include <cuda_runtime.h>
#include <cuda_bf16.h>
#include <cstdint>

#define B_SZ 4096
#define D_SZ 2048
#define E_SZ 16
#define C_SZ 1000
#define NPAD 1024

#define TM 128
#define TN 128
#define KC 32
#define NCHUNK (D_SZ / KC)      // 64

// A smem: [m][k] rows of 64B padded to 80B (ldmatrix conflict-free)
#define ROWB 80
#define A_TILE_B (128 * ROWB)               // 10240
// B smem: [k][n] rows of 256B padded to 272B (17 segs -> trans conflict-free)
#define BROWB 272
#define B_TILE_B (KC * BROWB)               // 8704
#define OFF_AH 0
#define OFF_AL A_TILE_B
#define OFF_BH (2 * A_TILE_B)
#define OFF_BL (2 * A_TILE_B + B_TILE_B)
#define STAGE_B (2 * A_TILE_B + 2 * B_TILE_B)   // 37888
#define NST 2
#define DYN_BYTES (NST * STAGE_B)               // 75776 -> 2 CTAs/SM

// gate split
#define GR 16
#define GP 4
#define DPG (D_SZ / GP)
#define GCH (DPG / 128)

// ---------------- scratch ----------------
__device__ int   g_cnt[E_SZ];
__device__ int   g_rows[E_SZ * B_SZ];
__device__ float g_rw[E_SZ * B_SZ];
__device__ float g_part[GP][B_SZ][E_SZ];
__device__ __nv_bfloat16 x_h[(size_t)B_SZ * D_SZ];
__device__ __nv_bfloat16 x_l[(size_t)B_SZ * D_SZ];
__device__ __nv_bfloat16 w_h[(size_t)E_SZ * D_SZ * NPAD];  // [e][k][n]
__device__ __nv_bfloat16 w_l[(size_t)E_SZ * D_SZ * NPAD];

// ---------------- helpers ----------------
__device__ __forceinline__ uint32_t smem_u32(const void* p) {
    uint32_t a;
    asm("{ .reg .u64 t; cvta.to.shared.u64 t, %1; cvt.u32.u64 %0, t; }"
        : "=r"(a) : "l"(p));
    return a;
}
__device__ __forceinline__ void split_pack(float a, float b, uint32_t& h, uint32_t& l) {
    __nv_bfloat162 hh = __floats2bfloat162_rn(a, b);
    float ra = a - __bfloat162float(hh.x);
    float rb = b - __bfloat162float(hh.y);
    __nv_bfloat162 ll = __floats2bfloat162_rn(ra, rb);
    h = *reinterpret_cast<uint32_t*>(&hh);
    l = *reinterpret_cast<uint32_t*>(&ll);
}
__device__ __forceinline__ void cpa16(uint32_t dst, const void* src) {
    asm volatile("cp.async.ca.shared.global [%0], [%1], 16;"
                 :: "r"(dst), "l"(src));
}
#define CP_COMMIT() asm volatile("cp.async.commit_group;" ::: "memory")
#define CP_WAITN(n) asm volatile("cp.async.wait_group %0;" :: "n"(n) : "memory")
#define LDSM4(r, addr)                                                        \
    asm volatile("ldmatrix.sync.aligned.m8n8.x4.shared.b16 {%0,%1,%2,%3}, [%4];" \
                 : "=r"((r)[0]), "=r"((r)[1]), "=r"((r)[2]), "=r"((r)[3])     \
                 : "r"(addr))
#define LDSM4T(r, addr)                                                       \
    asm volatile("ldmatrix.sync.aligned.m8n8.x4.trans.shared.b16 {%0,%1,%2,%3}, [%4];" \
                 : "=r"((r)[0]), "=r"((r)[1]), "=r"((r)[2]), "=r"((r)[3])     \
                 : "r"(addr))
#define MMA16816(c, a, b0, b1)                                                \
    asm volatile("mma.sync.aligned.m16n8k16.row.col.f32.bf16.bf16.f32 "       \
                 "{%0,%1,%2,%3}, {%4,%5,%6,%7}, {%8,%9}, {%0,%1,%2,%3};"      \
                 : "+f"((c)[0]), "+f"((c)[1]), "+f"((c)[2]), "+f"((c)[3])     \
                 : "r"((a)[0]), "r"((a)[1]), "r"((a)[2]), "r"((a)[3]),        \
                   "r"(b0), "r"(b1))

// ---------------- kernel 1: zero output + expert counts ----------------
__global__ void zero_kernel(float4* __restrict__ out, int n4) {
    int i = blockIdx.x * blockDim.x + threadIdx.x;
    if (i < n4) out[i] = make_float4(0.f, 0.f, 0.f, 0.f);
    if (i < E_SZ) g_cnt[i] = 0;
}

// ---------------- kernel 2: convert x -> bf16 hi/lo (stream) ---------------
__global__ void conv_x(const float4* __restrict__ xin, int n4) {
    int i = blockIdx.x * blockDim.x + threadIdx.x;
    if (i >= n4) return;
    float4 v = xin[i];
    uint32_t h0, l0, h1, l1;
    split_pack(v.x, v.y, h0, l0);
    split_pack(v.z, v.w, h1, l1);
    reinterpret_cast<uint2*>(x_h)[i] = make_uint2(h0, h1);
    reinterpret_cast<uint2*>(x_l)[i] = make_uint2(l0, l1);
}

// ---------------- kernel 3: convert We -> bf16 hi/lo, [e][k][n], pad n -----
__global__ __launch_bounds__(256) void conv_w(const float* __restrict__ We) {
    const size_t row = blockIdx.x;              // e*D_SZ + k
    const int t = threadIdx.x;
    const float* src = We + row * C_SZ;
    uint2* dh = reinterpret_cast<uint2*>(w_h + row * NPAD);
    uint2* dl = reinterpret_cast<uint2*>(w_l + row * NPAD);
    if (t < 250) {
        float4 v = *reinterpret_cast<const float4*>(src + 4 * t);
        uint32_t h0, l0, h1, l1;
        split_pack(v.x, v.y, h0, l0);
        split_pack(v.z, v.w, h1, l1);
        dh[t] = make_uint2(h0, h1);
        dl[t] = make_uint2(l0, l1);
    } else {
        dh[t] = make_uint2(0u, 0u);
        dl[t] = make_uint2(0u, 0u);
    }
}

// ---------------- kernel 4: gate partials (split-D) ----------------
__global__ __launch_bounds__(256) void gate_part(
    const float* __restrict__ x, const float* __restrict__ Wr)
{
    __shared__ __align__(16) float xs[2][GR][132];
    __shared__ __align__(16) float wrs[2][E_SZ][132];

    const int tid   = threadIdx.x;
    const int row0  = blockIdx.x * GR;
    const int dbase = blockIdx.y * DPG;
    const int e     = tid & 15;
    const int r     = tid >> 4;

    const int xrow = tid >> 4;
    const int xseg = tid & 15;
    const float* xsrc = x + (size_t)(row0 + xrow) * D_SZ + dbase;
    const int wd = tid >> 1;
    const int we = (tid & 1) * 8;

    float4 wr0, wr1;
    auto ldg_wr = [&](int ch) {
        const float* p = Wr + (size_t)(dbase + ch * 128 + wd) * E_SZ + we;
        wr0 = *reinterpret_cast<const float4*>(p);
        wr1 = *reinterpret_cast<const float4*>(p + 4);
    };
    auto sts_wr = [&](int s) {
        wrs[s][we + 0][wd] = wr0.x; wrs[s][we + 1][wd] = wr0.y;
        wrs[s][we + 2][wd] = wr0.z; wrs[s][we + 3][wd] = wr0.w;
        wrs[s][we + 4][wd] = wr1.x; wrs[s][we + 5][wd] = wr1.y;
        wrs[s][we + 6][wd] = wr1.z; wrs[s][we + 7][wd] = wr1.w;
    };
    auto cpa_xs = [&](int ch, int s) {
        const int d0 = ch * 128;
        cpa16(smem_u32(&xs[s][xrow][xseg * 4]),        xsrc + d0 + xseg * 4);
        cpa16(smem_u32(&xs[s][xrow][(xseg + 16) * 4]), xsrc + d0 + (xseg + 16) * 4);
    };

    float acc0 = 0.0f, acc1 = 0.0f;

    ldg_wr(0);
    cpa_xs(0, 0); CP_COMMIT();
    for (int ch = 0; ch < GCH; ch++) {
        const int s = ch & 1;
        sts_wr(s);
        if (ch + 1 < GCH) {
            ldg_wr(ch + 1);
            cpa_xs(ch + 1, s ^ 1); CP_COMMIT();
            CP_WAITN(1);
        } else {
            CP_WAITN(0);
        }
        __syncthreads();
#pragma unroll
        for (int d = 0; d < 64; d += 4) {
            float4 xa = *reinterpret_cast<const float4*>(&xs[s][r][d]);
            float4 wa = *reinterpret_cast<const float4*>(&wrs[s][e][d]);
            acc0 += xa.x * wa.x + xa.y * wa.y + xa.z * wa.z + xa.w * wa.w;
            float4 xb = *reinterpret_cast<const float4*>(&xs[s][r][d + 64]);
            float4 wb = *reinterpret_cast<const float4*>(&wrs[s][e][d + 64]);
            acc1 += xb.x * wb.x + xb.y * wb.y + xb.z * wb.z + xb.w * wb.w;
        }
        __syncthreads();
    }
    g_part[blockIdx.y][row0 + r][e] = acc0 + acc1;
}

// ---------------- kernel 5: reduce partials + top-2 softmax + bucket -------
__global__ __launch_bounds__(256) void gate_reduce(const float* __restrict__ br) {
    const int row = blockIdx.x * 256 + threadIdx.x;
    if (row >= B_SZ) return;

    float lg[E_SZ];
#pragma unroll
    for (int q = 0; q < 4; q++) {
        float4 s = make_float4(0.f, 0.f, 0.f, 0.f);
#pragma unroll
        for (int p = 0; p < GP; p++) {
            float4 v = *reinterpret_cast<const float4*>(&g_part[p][row][q * 4]);
            s.x += v.x; s.y += v.y; s.z += v.z; s.w += v.w;
        }
        lg[q * 4 + 0] = s.x + br[q * 4 + 0];
        lg[q * 4 + 1] = s.y + br[q * 4 + 1];
        lg[q * 4 + 2] = s.z + br[q * 4 + 2];
        lg[q * 4 + 3] = s.w + br[q * 4 + 3];
    }

    float best = -1e30f; int bi = 0;
#pragma unroll
    for (int k = 0; k < E_SZ; k++)
        if (lg[k] > best) { best = lg[k]; bi = k; }
    float sec = -1e30f; int si = 0;
#pragma unroll
    for (int k = 0; k < E_SZ; k++) {
        if (k == bi) continue;
        if (lg[k] > sec) { sec = lg[k]; si = k; }
    }
    float t   = expf(sec - best);
    float inv = 1.0f / (1.0f + t);
    int p0 = atomicAdd(&g_cnt[bi], 1);
    g_rows[bi * B_SZ + p0] = row;  g_rw[bi * B_SZ + p0] = inv;
    int p1 = atomicAdd(&g_cnt[si], 1);
    g_rows[si * B_SZ + p1] = row;  g_rw[si * B_SZ + p1] = t * inv;
}

// ---------------- kernel 6: 2-CTA/SM cp.async mma.sync gather-GEMM ---------
// TM128 x TN128, warp tile 64x32, __launch_bounds__(256,2) caps regs at 128
// so 2 CTAs co-reside -> 4 warps/SMSP to hide the bubbles R11 exposed
// (tensor 52.5%, occ 12.5%).
extern __shared__ char dynsmem[];

__global__ __launch_bounds__(256, 2) void expert_gemm_mma(
    const float* __restrict__ be, float* __restrict__ out)
{
    const int e   = blockIdx.z;
    const int cnt = g_cnt[e];
    const int m0  = blockIdx.y * TM;
    if (m0 >= cnt) return;
    const int n0  = blockIdx.x * TN;

    __shared__ int   rs[TM];
    __shared__ float ws[TM];
    __shared__ float bes[TN];

    const int tid  = threadIdx.x;
    const int wid  = tid >> 5;
    const int lane = tid & 31;

    const uint32_t sb0 = smem_u32(dynsmem);

    for (int m = tid; m < TM; m += 256) {
        int gm = m0 + m; int rr = -1; float w = 0.0f;
        if (gm < cnt) { rr = g_rows[e * B_SZ + gm]; w = g_rw[e * B_SZ + gm]; }
        rs[m] = rr; ws[m] = w;
    }
    if (tid < TN) {
        int c = n0 + tid;
        bes[tid] = (c < C_SZ) ? be[e * C_SZ + c] : 0.0f;
    }
    __syncthreads();

    // ---- cp.async mappings: 8 x 16B per thread per chunk ----
    // A: row am = tid>>1, k-half t2 = tid&1 (two 16B segs each for h and l)
    const int am = tid >> 1;
    const int t2 = tid & 1;
    int ra = rs[am]; if (ra < 0) ra = 0;
    const __nv_bfloat16* srcAh = x_h + (size_t)ra * D_SZ + t2 * 16;
    const __nv_bfloat16* srcAl = x_l + (size_t)ra * D_SZ + t2 * 16;
    const uint32_t aoff = (uint32_t)(am * ROWB + t2 * 32);
    // B: k-rows kr and kr+16 (kr = tid>>4), n-seg sg = tid&15
    const int kr = tid >> 4;
    const int sg = tid & 15;
    const __nv_bfloat16* srcBh =
        w_h + ((size_t)e * D_SZ + kr) * NPAD + n0 + sg * 8;
    const __nv_bfloat16* srcBl =
        w_l + ((size_t)e * D_SZ + kr) * NPAD + n0 + sg * 8;
    const uint32_t boff = (uint32_t)(kr * BROWB + sg * 16);

    auto issue_stage = [&](int c, int slot) {
        const uint32_t sb = sb0 + (uint32_t)slot * STAGE_B;
        const int ko = c * KC;
        cpa16(sb + OFF_AH + aoff,      srcAh + ko);
        cpa16(sb + OFF_AH + aoff + 16, srcAh + ko + 8);
        cpa16(sb + OFF_AL + aoff,      srcAl + ko);
        cpa16(sb + OFF_AL + aoff + 16, srcAl + ko + 8);
        const size_t bko = (size_t)ko * NPAD;
        cpa16(sb + OFF_BH + boff,                srcBh + bko);
        cpa16(sb + OFF_BH + boff + 16 * BROWB,   srcBh + bko + (size_t)16 * NPAD);
        cpa16(sb + OFF_BL + boff,                srcBl + bko);
        cpa16(sb + OFF_BL + boff + 16 * BROWB,   srcBl + bko + (size_t)16 * NPAD);
        CP_COMMIT();
    };

    // ---- compute mappings: 2m x 4n warp grid, 64x32 warp tiles ----
    const int warp_m = (wid & 1) * 64;
    const int warp_n = (wid >> 1) * 32;
    const uint32_t a_lds =
        (uint32_t)((warp_m + (lane & 15)) * ROWB + (lane >> 4) * 16);
    // trans-B lane map (validated in R12): k-row = lane&15, n-half = lane>>4
    const uint32_t b_lds =
        (uint32_t)((lane & 15) * BROWB + ((lane >> 4) & 1) * 16 + warp_n * 2);

    float acc[4][4][4];
#pragma unroll
    for (int i = 0; i < 4; i++)
#pragma unroll
        for (int j = 0; j < 4; j++)
#pragma unroll
            for (int q = 0; q < 4; q++) acc[i][j][q] = 0.0f;

    auto compute_chunk = [&](int slot) {
        const uint32_t sb = sb0 + (uint32_t)slot * STAGE_B;
#pragma unroll
        for (int kk = 0; kk < 2; kk++) {
            uint32_t ah[4][4], al[4][4], bh[2][4], bl[2][4];
            const uint32_t bbase = sb + b_lds + kk * (16 * BROWB);
#pragma unroll
            for (int np = 0; np < 2; np++) {
                LDSM4T(bh[np], bbase + OFF_BH + np * 32);
                LDSM4T(bl[np], bbase + OFF_BL + np * 32);
            }
#pragma unroll
            for (int mt = 0; mt < 4; mt++) {
                const uint32_t ao = a_lds + mt * (16 * ROWB) + kk * 32;
                LDSM4(ah[mt], sb + OFF_AH + ao);
                LDSM4(al[mt], sb + OFF_AL + ao);
            }
#pragma unroll
            for (int mt = 0; mt < 4; mt++)
#pragma unroll
                for (int np = 0; np < 2; np++)
#pragma unroll
                    for (int nt = 0; nt < 2; nt++) {
                        float* a4 = acc[mt][np * 2 + nt];
                        uint32_t* bhf = &bh[np][nt * 2];
                        uint32_t* blf = &bl[np][nt * 2];
                        MMA16816(a4, ah[mt], bhf[0], bhf[1]);
                        MMA16816(a4, ah[mt], blf[0], blf[1]);
                        MMA16816(a4, al[mt], bhf[0], bhf[1]);
                    }
        }
    };

    // ---- main loop: 2-stage pipeline, two barriers per chunk ----
    issue_stage(0, 0);
    for (int c = 0; c < NCHUNK; c++) {
        const int slot = c & 1;
        if (c + 1 < NCHUNK) {
            issue_stage(c + 1, slot ^ 1);   // prev compute's slot: safe, barrier'd
            CP_WAITN(1);
        } else {
            CP_WAITN(0);
        }
        __syncthreads();                    // stage c visible block-wide
        compute_chunk(slot);
        __syncthreads();                    // slot free for next issue
    }

    // ---- epilogue: weighted atomic scatter ----
    const int gr = lane >> 2;
    const int gc = (lane & 3) * 2;
#pragma unroll
    for (int mt = 0; mt < 4; mt++) {
#pragma unroll
        for (int half = 0; half < 2; half++) {
            const int m = warp_m + mt * 16 + gr + half * 8;
            const int rr = rs[m];
            if (rr < 0) continue;
            const float w = ws[m];
            float* orow = out + (size_t)rr * C_SZ;
#pragma unroll
            for (int nt = 0; nt < 4; nt++) {
                const int cc = warp_n + nt * 8 + gc;
                const int c = n0 + cc;
                if (c >= C_SZ) continue;
                const float v0 = acc[mt][nt][half * 2 + 0];
                const float v1 = acc[mt][nt][half * 2 + 1];
                atomicAdd(orow + c,     w * (v0 + bes[cc]));
                atomicAdd(orow + c + 1, w * (v1 + bes[cc + 1]));
            }
        }
    }
}

// ---------------- launch ----------------
extern "C" void kernel_launch(void* const* d_in, const int* in_sizes, int n_in,
                              void* d_out, int out_size) {
    const float* x  = (const float*)d_in[0];
    const float* Wr = (const float*)d_in[1];
    const float* br = (const float*)d_in[2];
    const float* We = (const float*)d_in[3];
    const float* be = (const float*)d_in[4];
    float* out = (float*)d_out;

    cudaFuncSetAttribute(expert_gemm_mma,
                         cudaFuncAttributeMaxDynamicSharedMemorySize, DYN_BYTES);

    const int n4 = (B_SZ * C_SZ) / 4;
    zero_kernel<<<(n4 + 255) / 256, 256>>>((float4*)out, n4);
    const int nx4 = (B_SZ * D_SZ) / 4;
    conv_x<<<(nx4 + 255) / 256, 256>>>((const float4*)x, nx4);
    conv_w<<<E_SZ * D_SZ, 256>>>(We);
    dim3 ggrid(B_SZ / GR, GP);
    gate_part<<<ggrid, 256>>>(x, Wr);
    gate_reduce<<<B_SZ / 256, 256>>>(br);
    dim3 grid((C_SZ + TN - 1) / TN, B_SZ / TM, E_SZ);
    expert_gemm_mma<<<grid, 256, DYN_BYTES>>>(be, out);
}

// round 14
// speedup vs baseline: 1.3091x; 1.0426x over previous
#include <cuda_runtime.h>
#include <cuda_bf16.h>
#include <cstdint>

#define B_SZ 4096
#define D_SZ 2048
#define E_SZ 16
#define C_SZ 1000
#define NPAD 1024

// int8 GEMM tiles
#define TM 128
#define TN 64
#define KC 64                    // s8 k per chunk
#define NCHUNK (D_SZ / KC)       // 32

// A smem: [m][k] rows of 64 s8 padded to 80B; B smem: [n][k] same
#define AROWB 80
#define A_TILE_B (128 * AROWB)   // 10240 per limb
#define B_TILE_B (64 * AROWB)    // 5120 per limb
#define OFF_A1 0
#define OFF_A2 A_TILE_B
#define OFF_B1 (2 * A_TILE_B)
#define OFF_B2 (2 * A_TILE_B + B_TILE_B)
#define STAGE_B (2 * A_TILE_B + 2 * B_TILE_B)   // 30720
#define NST 2
#define DYN_BYTES (NST * STAGE_B)               // 61440 -> 2 CTAs/SM

#define QSCALE 16319.0f
#define XLIMB ((size_t)B_SZ * D_SZ)
#define WLIMB ((size_t)E_SZ * NPAD * D_SZ)

// gate split
#define GR 16
#define GP 4
#define DPG (D_SZ / GP)
#define GCH (DPG / 128)

// ---------------- scratch ----------------
__device__ int    g_cnt[E_SZ];
__device__ int    g_rows[E_SZ * B_SZ];
__device__ float  g_rw[E_SZ * B_SZ];
__device__ float  g_part[GP][B_SZ][E_SZ];
__device__ int8_t xq[2][XLIMB];            // x limbs [limb][row][k]
__device__ int8_t wq[2][WLIMB];            // W limbs [limb][e][n][k]
__device__ float  sxg[B_SZ];               // per-row x scale
__device__ float  swg[E_SZ * NPAD];        // per-(e,n) W scale
__device__ int    wmaxg[E_SZ * NPAD];      // float-bits col max (atomicMax)

// ---------------- helpers ----------------
__device__ __forceinline__ uint32_t smem_u32(const void* p) {
    uint32_t a;
    asm("{ .reg .u64 t; cvta.to.shared.u64 t, %1; cvt.u32.u64 %0, t; }"
        : "=r"(a) : "l"(p));
    return a;
}
__device__ __forceinline__ void cpa16(uint32_t dst, const void* src) {
    asm volatile("cp.async.ca.shared.global [%0], [%1], 16;"
                 :: "r"(dst), "l"(src));
}
#define CP_COMMIT() asm volatile("cp.async.commit_group;" ::: "memory")
#define CP_WAITN(n) asm volatile("cp.async.wait_group %0;" :: "n"(n) : "memory")
#define LDSM4(r, addr)                                                        \
    asm volatile("ldmatrix.sync.aligned.m8n8.x4.shared.b16 {%0,%1,%2,%3}, [%4];" \
                 : "=r"((r)[0]), "=r"((r)[1]), "=r"((r)[2]), "=r"((r)[3])     \
                 : "r"(addr))
#define IMMA(c, a, b0, b1)                                                    \
    asm volatile("mma.sync.aligned.m16n8k32.row.col.s32.s8.s8.s32 "           \
                 "{%0,%1,%2,%3}, {%4,%5,%6,%7}, {%8,%9}, {%0,%1,%2,%3};"      \
                 : "+r"((c)[0]), "+r"((c)[1]), "+r"((c)[2]), "+r"((c)[3])     \
                 : "r"((a)[0]), "r"((a)[1]), "r"((a)[2]), "r"((a)[3]),        \
                   "r"(b0), "r"(b1))

__device__ __forceinline__ uint32_t pack4(int a, int b, int c, int d) {
    return (uint32_t)(a & 255) | ((uint32_t)(b & 255) << 8) |
           ((uint32_t)(c & 255) << 16) | ((uint32_t)(d & 255) << 24);
}

// ---------------- kernel 1: zero output + counters + wmax ----------------
__global__ void zero_kernel(float4* __restrict__ out, int n4) {
    int i = blockIdx.x * blockDim.x + threadIdx.x;
    if (i < n4) out[i] = make_float4(0.f, 0.f, 0.f, 0.f);
    if (i < E_SZ) g_cnt[i] = 0;
    if (i < E_SZ * NPAD) wmaxg[i] = 0;
}

// ---------------- kernel 2: quantize x -> 2 s8 limbs + row scale -----------
__global__ __launch_bounds__(256) void quant_x(const float* __restrict__ x) {
    const int row = blockIdx.x;
    const int t   = threadIdx.x;
    __shared__ float red[256];

    const float4* xr = reinterpret_cast<const float4*>(x + (size_t)row * D_SZ);
    float4 v0 = xr[2 * t], v1 = xr[2 * t + 1];
    float m = fmaxf(fmaxf(fabsf(v0.x), fabsf(v0.y)), fmaxf(fabsf(v0.z), fabsf(v0.w)));
    m = fmaxf(m, fmaxf(fmaxf(fabsf(v1.x), fabsf(v1.y)), fmaxf(fabsf(v1.z), fabsf(v1.w))));
    red[t] = m;
    __syncthreads();
    for (int s = 128; s > 0; s >>= 1) {
        if (t < s) red[t] = fmaxf(red[t], red[t + s]);
        __syncthreads();
    }
    const float maxv = red[0];
    const float inv  = maxv > 0.f ? QSCALE / maxv : 0.f;

    float vv[8] = {v0.x, v0.y, v0.z, v0.w, v1.x, v1.y, v1.z, v1.w};
    int q1[8], q2[8];
#pragma unroll
    for (int i = 0; i < 8; i++) {
        float tv  = vv[i] * inv;
        float h   = rintf(tv * 0.0078125f);     // /128
        q1[i] = (int)h;
        q2[i] = (int)rintf(tv - 128.f * h);
    }
    uint2 p1 = make_uint2(pack4(q1[0], q1[1], q1[2], q1[3]),
                          pack4(q1[4], q1[5], q1[6], q1[7]));
    uint2 p2 = make_uint2(pack4(q2[0], q2[1], q2[2], q2[3]),
                          pack4(q2[4], q2[5], q2[6], q2[7]));
    *reinterpret_cast<uint2*>(&xq[0][(size_t)row * D_SZ + t * 8]) = p1;
    *reinterpret_cast<uint2*>(&xq[1][(size_t)row * D_SZ + t * 8]) = p2;
    if (t == 0) sxg[row] = maxv * (1.0f / QSCALE);
}

// ---------------- kernel 3: per-(e,n) column max of |We| --------------------
__global__ __launch_bounds__(256) void wmax_kernel(const float* __restrict__ We) {
    const int nb = blockIdx.x, kb = blockIdx.y, e = blockIdx.z;
    const int n = nb * 256 + threadIdx.x;
    if (n >= C_SZ) return;
    const float* src = We + ((size_t)e * D_SZ + kb * 256) * C_SZ + n;
    float m = 0.f;
#pragma unroll 4
    for (int k = 0; k < 256; k++)
        m = fmaxf(m, fabsf(src[(size_t)k * C_SZ]));
    atomicMax(&wmaxg[e * NPAD + n], __float_as_int(m));   // m >= 0
}

// ---------------- kernel 4: quantize+transpose We -> [e][n][k] limbs -------
__global__ __launch_bounds__(256) void quant_w(const float* __restrict__ We) {
    const int nb = blockIdx.x;     // 8 x 128n
    const int kb = blockIdx.y;     // 64 x 32k
    const int e  = blockIdx.z;
    const int t  = threadIdx.x;
    const int n0 = nb * 128, k0 = kb * 32;

    __shared__ float xs[32][132];
    for (int i = t; i < 32 * 128; i += 256) {
        int k = i >> 7, n = i & 127;
        xs[k][n] = (n0 + n < C_SZ)
            ? We[((size_t)e * D_SZ + k0 + k) * C_SZ + n0 + n] : 0.0f;
    }
    __syncthreads();

    const int n  = t >> 1;
    const int kh = (t & 1) * 16;
    const float mw  = __int_as_float(wmaxg[e * NPAD + n0 + n]);
    const float inv = mw > 0.f ? QSCALE / mw : 0.f;
    if (kb == 0 && kh == 0) swg[e * NPAD + n0 + n] = mw * (1.0f / QSCALE);

    int q1[16], q2[16];
#pragma unroll
    for (int j = 0; j < 16; j++) {
        float tv = xs[kh + j][n] * inv;
        float h  = rintf(tv * 0.0078125f);
        q1[j] = (int)h;
        q2[j] = (int)rintf(tv - 128.f * h);
    }
    const size_t base = ((size_t)(e * NPAD + n0 + n)) * D_SZ + k0 + kh;
    *reinterpret_cast<uint4*>(&wq[0][base]) =
        make_uint4(pack4(q1[0], q1[1], q1[2], q1[3]),  pack4(q1[4], q1[5], q1[6], q1[7]),
                   pack4(q1[8], q1[9], q1[10], q1[11]), pack4(q1[12], q1[13], q1[14], q1[15]));
    *reinterpret_cast<uint4*>(&wq[1][base]) =
        make_uint4(pack4(q2[0], q2[1], q2[2], q2[3]),  pack4(q2[4], q2[5], q2[6], q2[7]),
                   pack4(q2[8], q2[9], q2[10], q2[11]), pack4(q2[12], q2[13], q2[14], q2[15]));
}

// ---------------- kernel 5: gate partials (split-D, unchanged) -------------
__global__ __launch_bounds__(256) void gate_part(
    const float* __restrict__ x, const float* __restrict__ Wr)
{
    __shared__ __align__(16) float xs[2][GR][132];
    __shared__ __align__(16) float wrs[2][E_SZ][132];

    const int tid   = threadIdx.x;
    const int row0  = blockIdx.x * GR;
    const int dbase = blockIdx.y * DPG;
    const int e     = tid & 15;
    const int r     = tid >> 4;

    const int xrow = tid >> 4;
    const int xseg = tid & 15;
    const float* xsrc = x + (size_t)(row0 + xrow) * D_SZ + dbase;
    const int wd = tid >> 1;
    const int we = (tid & 1) * 8;

    float4 wr0, wr1;
    auto ldg_wr = [&](int ch) {
        const float* p = Wr + (size_t)(dbase + ch * 128 + wd) * E_SZ + we;
        wr0 = *reinterpret_cast<const float4*>(p);
        wr1 = *reinterpret_cast<const float4*>(p + 4);
    };
    auto sts_wr = [&](int s) {
        wrs[s][we + 0][wd] = wr0.x; wrs[s][we + 1][wd] = wr0.y;
        wrs[s][we + 2][wd] = wr0.z; wrs[s][we + 3][wd] = wr0.w;
        wrs[s][we + 4][wd] = wr1.x; wrs[s][we + 5][wd] = wr1.y;
        wrs[s][we + 6][wd] = wr1.z; wrs[s][we + 7][wd] = wr1.w;
    };
    auto cpa_xs = [&](int ch, int s) {
        const int d0 = ch * 128;
        cpa16(smem_u32(&xs[s][xrow][xseg * 4]),        xsrc + d0 + xseg * 4);
        cpa16(smem_u32(&xs[s][xrow][(xseg + 16) * 4]), xsrc + d0 + (xseg + 16) * 4);
    };

    float acc0 = 0.0f, acc1 = 0.0f;

    ldg_wr(0);
    cpa_xs(0, 0); CP_COMMIT();
    for (int ch = 0; ch < GCH; ch++) {
        const int s = ch & 1;
        sts_wr(s);
        if (ch + 1 < GCH) {
            ldg_wr(ch + 1);
            cpa_xs(ch + 1, s ^ 1); CP_COMMIT();
            CP_WAITN(1);
        } else {
            CP_WAITN(0);
        }
        __syncthreads();
#pragma unroll
        for (int d = 0; d < 64; d += 4) {
            float4 xa = *reinterpret_cast<const float4*>(&xs[s][r][d]);
            float4 wa = *reinterpret_cast<const float4*>(&wrs[s][e][d]);
            acc0 += xa.x * wa.x + xa.y * wa.y + xa.z * wa.z + xa.w * wa.w;
            float4 xb = *reinterpret_cast<const float4*>(&xs[s][r][d + 64]);
            float4 wb = *reinterpret_cast<const float4*>(&wrs[s][e][d + 64]);
            acc1 += xb.x * wb.x + xb.y * wb.y + xb.z * wb.z + xb.w * wb.w;
        }
        __syncthreads();
    }
    g_part[blockIdx.y][row0 + r][e] = acc0 + acc1;
}

// ---------------- kernel 6: reduce partials + top-2 softmax + bucket -------
__global__ __launch_bounds__(256) void gate_reduce(const float* __restrict__ br) {
    const int row = blockIdx.x * 256 + threadIdx.x;
    if (row >= B_SZ) return;

    float lg[E_SZ];
#pragma unroll
    for (int q = 0; q < 4; q++) {
        float4 s = make_float4(0.f, 0.f, 0.f, 0.f);
#pragma unroll
        for (int p = 0; p < GP; p++) {
            float4 v = *reinterpret_cast<const float4*>(&g_part[p][row][q * 4]);
            s.x += v.x; s.y += v.y; s.z += v.z; s.w += v.w;
        }
        lg[q * 4 + 0] = s.x + br[q * 4 + 0];
        lg[q * 4 + 1] = s.y + br[q * 4 + 1];
        lg[q * 4 + 2] = s.z + br[q * 4 + 2];
        lg[q * 4 + 3] = s.w + br[q * 4 + 3];
    }

    float best = -1e30f; int bi = 0;
#pragma unroll
    for (int k = 0; k < E_SZ; k++)
        if (lg[k] > best) { best = lg[k]; bi = k; }
    float sec = -1e30f; int si = 0;
#pragma unroll
    for (int k = 0; k < E_SZ; k++) {
        if (k == bi) continue;
        if (lg[k] > sec) { sec = lg[k]; si = k; }
    }
    float t   = expf(sec - best);
    float inv = 1.0f / (1.0f + t);
    int p0 = atomicAdd(&g_cnt[bi], 1);
    g_rows[bi * B_SZ + p0] = row;  g_rw[bi * B_SZ + p0] = inv;
    int p1 = atomicAdd(&g_cnt[si], 1);
    g_rows[si * B_SZ + p1] = row;  g_rw[si * B_SZ + p1] = t * inv;
}

// ---------------- kernel 7: int8 limb IMMA grouped gather-GEMM -------------
// TM128 x TN64, 8 warps of 32x32, 2 CTAs/SM. Per logical k: 3 IMMA k32
// (X1W1 -> acc_hh; X1W2 + X2W1 -> acc_mid) = half the tensor cycles of the
// 3-term bf16 scheme. out = sx*sw*(16384*hh + 128*mid).
extern __shared__ char dynsmem[];

__global__ __launch_bounds__(256, 2) void expert_gemm_i8(
    const float* __restrict__ be, float* __restrict__ out)
{
    const int e   = blockIdx.z;
    const int cnt = g_cnt[e];
    const int m0  = blockIdx.y * TM;
    if (m0 >= cnt) return;
    const int n0  = blockIdx.x * TN;

    __shared__ int   rs[TM];
    __shared__ float ws[TM];
    __shared__ float sxs[TM];
    __shared__ float bes[TN];
    __shared__ float sws[TN];

    const int tid  = threadIdx.x;
    const int wid  = tid >> 5;
    const int lane = tid & 31;

    const uint32_t sb0 = smem_u32(dynsmem);

    for (int m = tid; m < TM; m += 256) {
        int gm = m0 + m; int rr = -1; float w = 0.0f; float sx = 0.0f;
        if (gm < cnt) {
            rr = g_rows[e * B_SZ + gm];
            w  = g_rw[e * B_SZ + gm];
            sx = sxg[rr];
        }
        rs[m] = rr; ws[m] = w; sxs[m] = sx;
    }
    if (tid < TN) {
        int c = n0 + tid;
        bes[tid] = (c < C_SZ) ? be[e * C_SZ + c] : 0.0f;
        sws[tid] = swg[e * NPAD + c];
    }
    __syncthreads();

    // ---- cp.async mappings: 6 x 16B per thread per chunk ----
    // A: row am = tid>>1, two segs at (tid&1)*32
    const int am = tid >> 1;
    const int as = (tid & 1) * 32;
    int ra = rs[am]; if (ra < 0) ra = 0;
    const int8_t* srcA = xq[0] + (size_t)ra * D_SZ + as;
    const uint32_t aoff = (uint32_t)(am * AROWB + as);
    // B: row bn = tid>>2, seg (tid&3)*16
    const int bn = tid >> 2;
    const int bs = (tid & 3) * 16;
    const int8_t* srcB = wq[0] + ((size_t)(e * NPAD + n0 + bn)) * D_SZ + bs;
    const uint32_t boff = (uint32_t)(bn * AROWB + bs);

    auto issue_stage = [&](int c, int slot) {
        const uint32_t sb = sb0 + (uint32_t)slot * STAGE_B;
        const int ko = c * KC;
        cpa16(sb + OFF_A1 + aoff,      srcA + ko);
        cpa16(sb + OFF_A1 + aoff + 16, srcA + ko + 16);
        cpa16(sb + OFF_A2 + aoff,      srcA + XLIMB + ko);
        cpa16(sb + OFF_A2 + aoff + 16, srcA + XLIMB + ko + 16);
        cpa16(sb + OFF_B1 + boff, srcB + ko);
        cpa16(sb + OFF_B2 + boff, srcB + WLIMB + ko);
        CP_COMMIT();
    };

    // ---- compute mappings: 4m x 2n warp grid, 32x32 warp tiles ----
    const int warp_m = (wid & 3) * 32;
    const int warp_n = (wid >> 2) * 32;
    const uint32_t a_lds =
        (uint32_t)((warp_m + (lane & 15)) * AROWB + (lane >> 4) * 16);
    const uint32_t b_lds =
        (uint32_t)((warp_n + (lane & 15)) * AROWB + (lane >> 4) * 16);

    int acc1[2][4][4], acc2[2][4][4];
#pragma unroll
    for (int i = 0; i < 2; i++)
#pragma unroll
        for (int j = 0; j < 4; j++)
#pragma unroll
            for (int q = 0; q < 4; q++) { acc1[i][j][q] = 0; acc2[i][j][q] = 0; }

    auto compute_chunk = [&](int slot) {
        const uint32_t sb = sb0 + (uint32_t)slot * STAGE_B;
#pragma unroll
        for (int kk = 0; kk < 2; kk++) {
            const uint32_t koff = kk * 32;
            uint32_t a1[2][4], a2[2][4], b1f[2][4], b2f[2][4];
            LDSM4(b1f[0], sb + OFF_B1 + b_lds + koff);
            LDSM4(b1f[1], sb + OFF_B1 + b_lds + 16 * AROWB + koff);
            LDSM4(b2f[0], sb + OFF_B2 + b_lds + koff);
            LDSM4(b2f[1], sb + OFF_B2 + b_lds + 16 * AROWB + koff);
#pragma unroll
            for (int mt = 0; mt < 2; mt++) {
                const uint32_t ao = a_lds + mt * (16 * AROWB) + koff;
                LDSM4(a1[mt], sb + OFF_A1 + ao);
                LDSM4(a2[mt], sb + OFF_A2 + ao);
            }
#pragma unroll
            for (int mt = 0; mt < 2; mt++)
#pragma unroll
                for (int og = 0; og < 4; og++) {
                    const int g = og >> 1, j = og & 1;
                    const uint32_t p10 = b1f[g][j], p11 = b1f[g][j + 2];
                    const uint32_t p20 = b2f[g][j], p21 = b2f[g][j + 2];
                    IMMA(acc1[mt][og], a1[mt], p10, p11);
                    IMMA(acc2[mt][og], a1[mt], p20, p21);
                    IMMA(acc2[mt][og], a2[mt], p10, p11);
                }
        }
    };

    // ---- main loop: 2-stage pipeline ----
    issue_stage(0, 0);
    for (int c = 0; c < NCHUNK; c++) {
        const int slot = c & 1;
        if (c + 1 < NCHUNK) {
            issue_stage(c + 1, slot ^ 1);
            CP_WAITN(1);
        } else {
            CP_WAITN(0);
        }
        __syncthreads();
        compute_chunk(slot);
        __syncthreads();
    }

    // ---- epilogue: rescale + weighted atomic scatter ----
    const int gr = lane >> 2;
    const int gc = (lane & 3) * 2;
#pragma unroll
    for (int mt = 0; mt < 2; mt++) {
#pragma unroll
        for (int half = 0; half < 2; half++) {
            const int m = warp_m + mt * 16 + gr + half * 8;
            const int rr = rs[m];
            if (rr < 0) continue;
            const float w  = ws[m];
            const float sx = sxs[m];
            float* orow = out + (size_t)rr * C_SZ;
#pragma unroll
            for (int og = 0; og < 4; og++) {
                const int cc = warp_n + og * 8 + gc;
                const int c = n0 + cc;
                if (c >= C_SZ) continue;
                const float v0 = 16384.f * (float)acc1[mt][og][half * 2 + 0] +
                                 128.f   * (float)acc2[mt][og][half * 2 + 0];
                const float v1 = 16384.f * (float)acc1[mt][og][half * 2 + 1] +
                                 128.f   * (float)acc2[mt][og][half * 2 + 1];
                atomicAdd(orow + c,     w * (sx * sws[cc] * v0 + bes[cc]));
                if (c + 1 < C_SZ)
                    atomicAdd(orow + c + 1, w * (sx * sws[cc + 1] * v1 + bes[cc + 1]));
            }
        }
    }
}

// ---------------- launch ----------------
extern "C" void kernel_launch(void* const* d_in, const int* in_sizes, int n_in,
                              void* d_out, int out_size) {
    const float* x  = (const float*)d_in[0];
    const float* Wr = (const float*)d_in[1];
    const float* br = (const float*)d_in[2];
    const float* We = (const float*)d_in[3];
    const float* be = (const float*)d_in[4];
    float* out = (float*)d_out;

    cudaFuncSetAttribute(expert_gemm_i8,
                         cudaFuncAttributeMaxDynamicSharedMemorySize, DYN_BYTES);

    const int n4 = (B_SZ * C_SZ) / 4;
    zero_kernel<<<(n4 + 255) / 256, 256>>>((float4*)out, n4);
    quant_x<<<B_SZ, 256>>>(x);
    dim3 wmgrid((C_SZ + 255) / 256, D_SZ / 256, E_SZ);
    wmax_kernel<<<wmgrid, 256>>>(We);
    dim3 wqgrid(NPAD / 128, D_SZ / 32, E_SZ);
    quant_w<<<wqgrid, 256>>>(We);
    dim3 ggrid(B_SZ / GR, GP);
    gate_part<<<ggrid, 256>>>(x, Wr);
    gate_reduce<<<B_SZ / 256, 256>>>(br);
    dim3 grid(NPAD / TN, B_SZ / TM, E_SZ);
    expert_gemm_i8<<<grid, 256, DYN_BYTES>>>(be, out);
}